// round 1
// baseline (speedup 1.0000x reference)
#include <cuda_runtime.h>
#include <math.h>

#define DIM 512
#define HID 256
#define KCL 16
#define NMAX 50000

// ---------------- scratch (device globals: alloc-free rule) ----------------
__device__ float g_bufA[NMAX * HID];   // X1 -> x_skip/x
__device__ float g_bufB[NMAX * HID];   // aggregation buffer
__device__ float g_bufC[NMAX * HID];   // X2pre -> x2
__device__ float g_deg_src[NMAX];
__device__ float g_deg_dst[NMAX];
__device__ float g_dis[NMAX];
__device__ float g_cs[KCL];
__device__ float g_dS[KCL];
__device__ float g_sc[2];              // [0]=trace_pooled, [1]=entropy sum

// ---------------- zero kernels ----------------
__global__ void zero_deg_kernel(int N) {
    int i = blockIdx.x * blockDim.x + threadIdx.x;
    if (i < N) { g_deg_src[i] = 0.f; g_deg_dst[i] = 0.f; }
}

__global__ void zero_misc_kernel(float* pooled) {
    int i = blockIdx.x * blockDim.x + threadIdx.x;
    if (i < KCL * DIM) pooled[i] = 0.f;
    if (i < KCL) { g_cs[i] = 0.f; g_dS[i] = 0.f; }
    if (i < 2) g_sc[i] = 0.f;
}

// ---------------- degrees ----------------
__global__ void degree_kernel(const int* __restrict__ src, const int* __restrict__ dst, int E) {
    int e = blockIdx.x * blockDim.x + threadIdx.x;
    if (e < E) {
        atomicAdd(&g_deg_src[src[e]], 1.f);
        atomicAdd(&g_deg_dst[dst[e]], 1.f);
    }
}

__global__ void dis_kernel(int N) {
    int i = blockIdx.x * blockDim.x + threadIdx.x;
    if (i < N) g_dis[i] = rsqrtf(1.f + g_deg_dst[i]);
}

// ---------------- fp32 tiled GEMM: C[M,Nd] = A[M,K] @ B[K,Nd] ----------------
// 64x64 tile, BK=16, 256 threads, 4x4 microtile.
__global__ void gemm64_kernel(const float* __restrict__ A, const float* __restrict__ B,
                              float* __restrict__ C, int M, int K, int Nd) {
    __shared__ __align__(16) float As[16][64];
    __shared__ __align__(16) float Bs[16][64];
    int tid = threadIdx.x;
    int row0 = blockIdx.x * 64;
    int col0 = blockIdx.y * 64;
    int ty = tid >> 4, tx = tid & 15;
    int ar = tid >> 2, ac4 = (tid & 3) * 4;     // A tile: 64 rows x 4 float4
    int br = tid >> 4, bc4 = (tid & 15) * 4;    // B tile: 16 rows x 16 float4
    float acc[4][4] = {};
    for (int k0 = 0; k0 < K; k0 += 16) {
        float4 av = make_float4(0.f, 0.f, 0.f, 0.f);
        if (row0 + ar < M)
            av = *(const float4*)(A + (size_t)(row0 + ar) * K + k0 + ac4);
        As[ac4 + 0][ar] = av.x; As[ac4 + 1][ar] = av.y;
        As[ac4 + 2][ar] = av.z; As[ac4 + 3][ar] = av.w;
        *(float4*)&Bs[br][bc4] = *(const float4*)(B + (size_t)(k0 + br) * Nd + col0 + bc4);
        __syncthreads();
        #pragma unroll
        for (int kk = 0; kk < 16; kk++) {
            float4 a4 = *(float4*)&As[kk][ty * 4];
            float4 b4 = *(float4*)&Bs[kk][tx * 4];
            float ra[4] = {a4.x, a4.y, a4.z, a4.w};
            float rb[4] = {b4.x, b4.y, b4.z, b4.w};
            #pragma unroll
            for (int i = 0; i < 4; i++)
                #pragma unroll
                for (int j = 0; j < 4; j++)
                    acc[i][j] += ra[i] * rb[j];
        }
        __syncthreads();
    }
    #pragma unroll
    for (int i = 0; i < 4; i++) {
        int row = row0 + ty * 4 + i;
        if (row < M)
            *(float4*)(C + (size_t)row * Nd + col0 + tx * 4) =
                make_float4(acc[i][0], acc[i][1], acc[i][2], acc[i][3]);
    }
}

// ---------------- AGG init: AGG = dis^2 * X (self-loop term folds in zeroing) ----------------
__global__ void init_agg_kernel(const float4* __restrict__ X, float4* __restrict__ AGG, int N) {
    int idx = blockIdx.x * blockDim.x + threadIdx.x;   // over N*64 float4s
    if (idx >= N * (HID / 4)) return;
    int i = idx >> 6;
    float dv = g_dis[i];
    float d2 = dv * dv;
    float4 v = X[idx];
    AGG[idx] = make_float4(v.x * d2, v.y * d2, v.z * d2, v.w * d2);
}

// ---------------- edge scatter: AGG[dst] += X[src] * dis[src]*dis[dst] (warp per edge) ----------------
__global__ void edge_scatter_kernel(const float* __restrict__ X, float* __restrict__ AGG,
                                    const int* __restrict__ src, const int* __restrict__ dst, int E) {
    int g = blockIdx.x * blockDim.x + threadIdx.x;
    int warp = g >> 5, lane = g & 31;
    if (warp >= E) return;
    int s = src[warp], d = dst[warp];
    float nrm = g_dis[s] * g_dis[d];
    const float4* xs = (const float4*)(X + (size_t)s * HID);
    float* ag = AGG + (size_t)d * HID;
    #pragma unroll
    for (int j = 0; j < 2; j++) {
        float4 v = xs[lane + 32 * j];
        int c = (lane + 32 * j) * 4;
        atomicAdd(ag + c + 0, v.x * nrm);
        atomicAdd(ag + c + 1, v.y * nrm);
        atomicAdd(ag + c + 2, v.z * nrm);
        atomicAdd(ag + c + 3, v.w * nrm);
    }
}

// ---------------- bias + SELU (+ optional skip) ----------------
__global__ void selu_bias_kernel(const float* __restrict__ AGG, const float* __restrict__ b,
                                 const float* __restrict__ skip, float* __restrict__ out, int total) {
    int idx = blockIdx.x * blockDim.x + threadIdx.x;
    if (idx >= total) return;
    const float alpha = 1.6732632423543772f;
    const float scale = 1.0507009873554805f;
    float v = AGG[idx] + b[idx & (HID - 1)];
    v = (v > 0.f) ? scale * v : scale * alpha * (expf(v) - 1.f);
    if (skip != nullptr) v += skip[idx];
    out[idx] = v;
}

// ---------------- logits -> softmax -> assignments + fused reductions ----------------
// 128 threads = 128 nodes per block. Staged X tile + Wa in shared.
__global__ void assign_kernel(const float* __restrict__ X, const float* __restrict__ Wa,
                              const float* __restrict__ ba, float* __restrict__ out, int N) {
    __shared__ __align__(16) float sWa[HID * KCL];   // 16 KB
    __shared__ __align__(16) float sX[128 * 33];     // padded, conflict-free
    __shared__ float sred[33];                        // 16 cs, 16 dS, 1 entropy
    int tid = threadIdx.x;
    for (int i = tid; i < HID * KCL; i += 128) sWa[i] = Wa[i];
    if (tid < 33) sred[tid] = 0.f;
    int node = blockIdx.x * 128 + tid;
    float acc[KCL];
    #pragma unroll
    for (int k = 0; k < KCL; k++) acc[k] = ba[k];

    for (int cb = 0; cb < HID; cb += 32) {
        __syncthreads();
        for (int idx = tid; idx < 128 * 32; idx += 128) {
            int ln = idx >> 5, c = idx & 31;
            int gn = blockIdx.x * 128 + ln;
            sX[ln * 33 + c] = (gn < N) ? X[(size_t)gn * HID + cb + c] : 0.f;
        }
        __syncthreads();
        #pragma unroll
        for (int cc = 0; cc < 32; cc++) {
            float xv = sX[tid * 33 + cc];
            const float4* w4 = (const float4*)&sWa[(cb + cc) * KCL];
            #pragma unroll
            for (int k4 = 0; k4 < 4; k4++) {
                float4 w = w4[k4];
                acc[k4 * 4 + 0] += xv * w.x;
                acc[k4 * 4 + 1] += xv * w.y;
                acc[k4 * 4 + 2] += xv * w.z;
                acc[k4 * 4 + 3] += xv * w.w;
            }
        }
    }

    if (node < N) {
        float mx = acc[0];
        #pragma unroll
        for (int k = 1; k < KCL; k++) mx = fmaxf(mx, acc[k]);
        float s = 0.f;
        #pragma unroll
        for (int k = 0; k < KCL; k++) { acc[k] = expf(acc[k] - mx); s += acc[k]; }
        float inv = 1.f / s;
        float ent = 0.f;
        float dgs = g_deg_src[node];
        #pragma unroll
        for (int k = 0; k < KCL; k++) {
            acc[k] *= inv;
            ent += acc[k] * logf(acc[k] + 1e-8f);
        }
        float4* o4 = (float4*)(out + (size_t)node * KCL);
        o4[0] = make_float4(acc[0], acc[1], acc[2], acc[3]);
        o4[1] = make_float4(acc[4], acc[5], acc[6], acc[7]);
        o4[2] = make_float4(acc[8], acc[9], acc[10], acc[11]);
        o4[3] = make_float4(acc[12], acc[13], acc[14], acc[15]);
        #pragma unroll
        for (int k = 0; k < KCL; k++) {
            atomicAdd(&sred[k], acc[k]);
            atomicAdd(&sred[16 + k], dgs * acc[k]);
        }
        atomicAdd(&sred[32], ent);
    }
    __syncthreads();
    if (tid < KCL) {
        atomicAdd(&g_cs[tid], sred[tid]);
        atomicAdd(&g_dS[tid], sred[16 + tid]);
    }
    if (tid == 32) atomicAdd(&g_sc[1], sred[32]);
}

// ---------------- trace(S^T A S) = sum over edges of <a[src], a[dst]> ----------------
__global__ void trace_kernel(const float* __restrict__ assign, const int* __restrict__ src,
                             const int* __restrict__ dst, int E) {
    int e = blockIdx.x * blockDim.x + threadIdx.x;
    float t = 0.f;
    if (e < E) {
        const float4* a = (const float4*)(assign + (size_t)src[e] * KCL);
        const float4* b = (const float4*)(assign + (size_t)dst[e] * KCL);
        #pragma unroll
        for (int j = 0; j < 4; j++) {
            float4 x = a[j], y = b[j];
            t += x.x * y.x + x.y * y.y + x.z * y.z + x.w * y.w;
        }
    }
    #pragma unroll
    for (int o = 16; o; o >>= 1) t += __shfl_down_sync(0xffffffffu, t, o);
    __shared__ float sw[8];
    if ((threadIdx.x & 31) == 0) sw[threadIdx.x >> 5] = t;
    __syncthreads();
    if (threadIdx.x < 8) {
        float v = sw[threadIdx.x];
        #pragma unroll
        for (int o = 4; o; o >>= 1) v += __shfl_down_sync(0xffu, v, o);
        if (threadIdx.x == 0) atomicAdd(&g_sc[0], v);
    }
}

// ---------------- pooled_raw[k,d] += sum_i a[i,k]*emb[i,d] ----------------
// block: 128-row i-chunk x 128-col d-chunk; thread owns one d, 16 k-accumulators.
__global__ void pooled_kernel(const float* __restrict__ assign, const float* __restrict__ emb,
                              float* __restrict__ pooled, int N) {
    __shared__ __align__(16) float sA[128 * KCL];
    int tid = threadIdx.x;  // 128
    int i0 = blockIdx.x * 128;
    int d = blockIdx.y * 128 + tid;
    for (int idx = tid; idx < 128 * KCL; idx += 128) {
        int gi = i0 + (idx >> 4);
        sA[idx] = (gi < N) ? assign[(size_t)gi * KCL + (idx & 15)] : 0.f;
    }
    __syncthreads();
    float acc[KCL] = {};
    int imax = min(128, N - i0);
    for (int i = 0; i < imax; i++) {
        float ev = emb[(size_t)(i0 + i) * DIM + d];
        const float4* a4 = (const float4*)&sA[i * KCL];
        #pragma unroll
        for (int k4 = 0; k4 < 4; k4++) {
            float4 a = a4[k4];
            acc[k4 * 4 + 0] += a.x * ev;
            acc[k4 * 4 + 1] += a.y * ev;
            acc[k4 * 4 + 2] += a.z * ev;
            acc[k4 * 4 + 3] += a.w * ev;
        }
    }
    #pragma unroll
    for (int k = 0; k < KCL; k++)
        atomicAdd(&pooled[k * DIM + d], acc[k]);
}

// ---------------- final: scale pooled by 1/(cs+eps), compute scalars ----------------
__global__ void final_kernel(float* __restrict__ out, int N, float m) {
    float* pooled = out + (size_t)N * KCL;
    int t = threadIdx.x;  // 512 threads == DIM
    #pragma unroll
    for (int k = 0; k < KCL; k++)
        pooled[k * DIM + t] *= 1.f / (g_cs[k] + 1e-8f);
    if (t == 0) {
        float dd = 0.f, csn = 0.f;
        #pragma unroll
        for (int k = 0; k < KCL; k++) { dd += g_dS[k] * g_dS[k]; csn += g_cs[k] * g_cs[k]; }
        float normalizer = dd / (2.f * m);
        float spectral = -(g_sc[0] - (float)KCL * normalizer) / (2.f * m);
        float collapse = sqrtf(csn) / (float)N * sqrtf((float)KCL) - 1.f;
        float entropy = -g_sc[1] / (float)N;
        float ent_loss = -0.1f * entropy;
        float total = spectral + collapse + ent_loss;
        float* s = pooled + KCL * DIM;
        s[0] = spectral;
        s[1] = collapse;
        s[2] = total;
        s[3] = ent_loss;
    }
}

// ---------------- launch ----------------
extern "C" void kernel_launch(void* const* d_in, const int* in_sizes, int n_in,
                              void* d_out, int out_size) {
    const float* emb  = (const float*)d_in[0];
    const int*   esrc = (const int*)d_in[1];
    const int*   edst = (const int*)d_in[2];
    const float* W1   = (const float*)d_in[3];
    const float* b1   = (const float*)d_in[4];
    const float* W2   = (const float*)d_in[5];
    const float* b2   = (const float*)d_in[6];
    const float* Wa   = (const float*)d_in[7];
    const float* ba   = (const float*)d_in[8];
    float* out = (float*)d_out;

    int E = in_sizes[1];
    int N = in_sizes[0] / DIM;
    float* pooled = out + (size_t)N * KCL;

    float *bufA, *bufB, *bufC;
    cudaGetSymbolAddress((void**)&bufA, g_bufA);
    cudaGetSymbolAddress((void**)&bufB, g_bufB);
    cudaGetSymbolAddress((void**)&bufC, g_bufC);

    int nb256 = (N + 255) / 256;
    int eb256 = (E + 255) / 256;
    int nh = N * HID;

    // reset accumulators (every replay)
    zero_deg_kernel<<<nb256, 256>>>(N);
    zero_misc_kernel<<<(KCL * DIM + 255) / 256, 256>>>(pooled);

    // degrees + symmetric norm
    degree_kernel<<<eb256, 256>>>(esrc, edst, E);
    dis_kernel<<<nb256, 256>>>(N);

    dim3 g1((N + 63) / 64, HID / 64);

    // ---- GCN layer 1 ----
    gemm64_kernel<<<g1, 256>>>(emb, W1, bufA, N, DIM, HID);
    init_agg_kernel<<<(N * (HID / 4) + 255) / 256, 256>>>((const float4*)bufA, (float4*)bufB, N);
    edge_scatter_kernel<<<(E * 32 + 255) / 256, 256>>>(bufA, bufB, esrc, edst, E);
    selu_bias_kernel<<<(nh + 255) / 256, 256>>>(bufB, b1, nullptr, bufA, nh);  // bufA = x = x_skip

    // ---- GCN layer 2 ----
    gemm64_kernel<<<g1, 256>>>(bufA, W2, bufC, N, HID, HID);
    init_agg_kernel<<<(N * (HID / 4) + 255) / 256, 256>>>((const float4*)bufC, (float4*)bufB, N);
    edge_scatter_kernel<<<(E * 32 + 255) / 256, 256>>>(bufC, bufB, esrc, edst, E);
    selu_bias_kernel<<<(nh + 255) / 256, 256>>>(bufB, b2, bufA, bufC, nh);     // bufC = x2 (+skip)

    // ---- assignments + fused cs/dS/entropy reductions ----
    assign_kernel<<<(N + 127) / 128, 128>>>(bufC, Wa, ba, out, N);

    // ---- trace over edges ----
    trace_kernel<<<eb256, 256>>>(out, esrc, edst, E);

    // ---- pooled ----
    pooled_kernel<<<dim3((N + 127) / 128, DIM / 128), 128>>>(out, emb, pooled, N);

    // ---- scalars + pooled normalization ----
    final_kernel<<<1, DIM>>>(out, N, 0.5f * (float)E);
}

// round 8
// speedup vs baseline: 1.0500x; 1.0500x over previous
#include <cuda_runtime.h>
#include <math.h>

#define DIM 512
#define HID 256
#define KCL 16
#define NMAX 50000

// ---------------- scratch (device globals: alloc-free rule) ----------------
__device__ float g_bufA[NMAX * HID];   // X1 -> x_skip/x
__device__ float g_bufB[NMAX * HID];   // aggregation buffer
__device__ float g_bufC[NMAX * HID];   // X2pre -> x2
__device__ float g_deg_src[NMAX];
__device__ float g_deg_dst[NMAX];
__device__ float g_dis[NMAX];
__device__ float g_cs[KCL];
__device__ float g_dS[KCL];
__device__ float g_sc[2];              // [0]=trace_pooled, [1]=entropy sum

// ---------------- zero kernels ----------------
__global__ void zero_deg_kernel(int N) {
    int i = blockIdx.x * blockDim.x + threadIdx.x;
    if (i < N) { g_deg_src[i] = 0.f; g_deg_dst[i] = 0.f; }
}

__global__ void zero_misc_kernel(float* pooled) {
    int i = blockIdx.x * blockDim.x + threadIdx.x;
    if (i < KCL * DIM) pooled[i] = 0.f;
    if (i < KCL) { g_cs[i] = 0.f; g_dS[i] = 0.f; }
    if (i < 2) g_sc[i] = 0.f;
}

// ---------------- degrees ----------------
__global__ void degree_kernel(const int* __restrict__ src, const int* __restrict__ dst, int E) {
    int e = blockIdx.x * blockDim.x + threadIdx.x;
    if (e < E) {
        atomicAdd(&g_deg_src[src[e]], 1.f);
        atomicAdd(&g_deg_dst[dst[e]], 1.f);
    }
}

__global__ void dis_kernel(int N) {
    int i = blockIdx.x * blockDim.x + threadIdx.x;
    if (i < N) g_dis[i] = rsqrtf(1.f + g_deg_dst[i]);
}

// ---------------- fp32 SGEMM 128x128x16, 8x8 microtile, double-buffered ----------------
// C[M,Nd] = A[M,K] @ B[K,Nd]; optionally also writes AGG = dis[row]^2 * C (fused self-loop init)
__global__ __launch_bounds__(256, 2)
void sgemm128_kernel(const float* __restrict__ A, const float* __restrict__ B,
                     float* __restrict__ C, float* __restrict__ AGG,
                     int M, int K, int Nd) {
    __shared__ __align__(16) float As[2][16][128];
    __shared__ __align__(16) float Bs[2][16][128];
    int tid = threadIdx.x;
    int row0 = blockIdx.x * 128;
    int col0 = blockIdx.y * 128;
    int tx = tid & 15, ty = tid >> 4;

    int arow = tid >> 2;          // 0..63 (x2 via +64)
    int acol = (tid & 3) * 4;     // 0,4,8,12
    int brow = tid >> 5;          // 0..7 (x2 via +8)
    int bcol = (tid & 31) * 4;    // 0..124

    const int nk = K >> 4;
    float4 a_reg[2], b_reg[2];

    // prefetch tile 0 -> regs
    #pragma unroll
    for (int i = 0; i < 2; i++) {
        int r = row0 + arow + i * 64;
        a_reg[i] = (r < M) ? *(const float4*)(A + (size_t)r * K + acol)
                           : make_float4(0.f, 0.f, 0.f, 0.f);
        b_reg[i] = *(const float4*)(B + (size_t)(brow + i * 8) * Nd + col0 + bcol);
    }
    // regs -> smem[0]
    #pragma unroll
    for (int i = 0; i < 2; i++) {
        As[0][acol + 0][arow + i * 64] = a_reg[i].x;
        As[0][acol + 1][arow + i * 64] = a_reg[i].y;
        As[0][acol + 2][arow + i * 64] = a_reg[i].z;
        As[0][acol + 3][arow + i * 64] = a_reg[i].w;
        *(float4*)&Bs[0][brow + i * 8][bcol] = b_reg[i];
    }
    __syncthreads();

    float acc[8][8] = {};
    for (int kb = 0; kb < nk; kb++) {
        int buf = kb & 1;
        if (kb + 1 < nk) {
            int k0 = (kb + 1) << 4;
            #pragma unroll
            for (int i = 0; i < 2; i++) {
                int r = row0 + arow + i * 64;
                a_reg[i] = (r < M) ? *(const float4*)(A + (size_t)r * K + k0 + acol)
                                   : make_float4(0.f, 0.f, 0.f, 0.f);
                b_reg[i] = *(const float4*)(B + (size_t)(k0 + brow + i * 8) * Nd + col0 + bcol);
            }
        }
        #pragma unroll
        for (int kk = 0; kk < 16; kk++) {
            float a[8], b[8];
            *(float4*)&a[0] = *(const float4*)&As[buf][kk][ty * 8];
            *(float4*)&a[4] = *(const float4*)&As[buf][kk][ty * 8 + 4];
            *(float4*)&b[0] = *(const float4*)&Bs[buf][kk][tx * 8];
            *(float4*)&b[4] = *(const float4*)&Bs[buf][kk][tx * 8 + 4];
            #pragma unroll
            for (int i = 0; i < 8; i++)
                #pragma unroll
                for (int j = 0; j < 8; j++)
                    acc[i][j] += a[i] * b[j];
        }
        if (kb + 1 < nk) {
            int nb = buf ^ 1;
            #pragma unroll
            for (int i = 0; i < 2; i++) {
                As[nb][acol + 0][arow + i * 64] = a_reg[i].x;
                As[nb][acol + 1][arow + i * 64] = a_reg[i].y;
                As[nb][acol + 2][arow + i * 64] = a_reg[i].z;
                As[nb][acol + 3][arow + i * 64] = a_reg[i].w;
                *(float4*)&Bs[nb][brow + i * 8][bcol] = b_reg[i];
            }
        }
        __syncthreads();
    }

    #pragma unroll
    for (int i = 0; i < 8; i++) {
        int row = row0 + ty * 8 + i;
        if (row >= M) break;
        float* crow = C + (size_t)row * Nd + col0 + tx * 8;
        float4 v0 = make_float4(acc[i][0], acc[i][1], acc[i][2], acc[i][3]);
        float4 v1 = make_float4(acc[i][4], acc[i][5], acc[i][6], acc[i][7]);
        *(float4*)crow = v0;
        *(float4*)(crow + 4) = v1;
        if (AGG != nullptr) {
            float dv = g_dis[row];
            float d2 = dv * dv;
            float* grow = AGG + (size_t)row * Nd + col0 + tx * 8;
            *(float4*)grow = make_float4(v0.x * d2, v0.y * d2, v0.z * d2, v0.w * d2);
            *(float4*)(grow + 4) = make_float4(v1.x * d2, v1.y * d2, v1.z * d2, v1.w * d2);
        }
    }
}

// ---------------- edge scatter: AGG[dst] += X[src] * dis[src]*dis[dst] ----------------
// warp per edge, scalar atomicAdd (proven-stable path)
__global__ void edge_scatter_kernel(const float* __restrict__ X, float* __restrict__ AGG,
                                    const int* __restrict__ src, const int* __restrict__ dst, int E) {
    int g = blockIdx.x * blockDim.x + threadIdx.x;
    int e = g >> 5, lane = g & 31;
    if (e >= E) return;
    int s = src[e], d = dst[e];
    float nrm = g_dis[s] * g_dis[d];
    const float4* xs = (const float4*)(X + (size_t)s * HID);
    float* ag = AGG + (size_t)d * HID;
    #pragma unroll
    for (int j = 0; j < 2; j++) {
        int q = lane + 32 * j;
        float4 v = xs[q];
        int c = q * 4;
        atomicAdd(ag + c + 0, v.x * nrm);
        atomicAdd(ag + c + 1, v.y * nrm);
        atomicAdd(ag + c + 2, v.z * nrm);
        atomicAdd(ag + c + 3, v.w * nrm);
    }
}

// ---------------- bias + SELU (+ optional skip) ----------------
__global__ void selu_bias_kernel(const float* __restrict__ AGG, const float* __restrict__ b,
                                 const float* __restrict__ skip, float* __restrict__ out, int total) {
    int idx = blockIdx.x * blockDim.x + threadIdx.x;
    if (idx >= total) return;
    const float alpha = 1.6732632423543772f;
    const float scale = 1.0507009873554805f;
    float v = AGG[idx] + b[idx & (HID - 1)];
    v = (v > 0.f) ? scale * v : scale * alpha * (expf(v) - 1.f);
    if (skip != nullptr) v += skip[idx];
    out[idx] = v;
}

// ---------------- logits -> softmax -> assignments + fused reductions ----------------
__global__ void assign_kernel(const float* __restrict__ X, const float* __restrict__ Wa,
                              const float* __restrict__ ba, float* __restrict__ out, int N) {
    __shared__ __align__(16) float sWa[HID * KCL];
    __shared__ __align__(16) float sX[128 * 33];
    __shared__ float sred[33];
    int tid = threadIdx.x;
    for (int i = tid; i < HID * KCL; i += 128) sWa[i] = Wa[i];
    if (tid < 33) sred[tid] = 0.f;
    int node = blockIdx.x * 128 + tid;
    float acc[KCL];
    #pragma unroll
    for (int k = 0; k < KCL; k++) acc[k] = ba[k];

    for (int cb = 0; cb < HID; cb += 32) {
        __syncthreads();
        for (int idx = tid; idx < 128 * 32; idx += 128) {
            int ln = idx >> 5, c = idx & 31;
            int gn = blockIdx.x * 128 + ln;
            sX[ln * 33 + c] = (gn < N) ? X[(size_t)gn * HID + cb + c] : 0.f;
        }
        __syncthreads();
        #pragma unroll
        for (int cc = 0; cc < 32; cc++) {
            float xv = sX[tid * 33 + cc];
            const float4* w4 = (const float4*)&sWa[(cb + cc) * KCL];
            #pragma unroll
            for (int k4 = 0; k4 < 4; k4++) {
                float4 w = w4[k4];
                acc[k4 * 4 + 0] += xv * w.x;
                acc[k4 * 4 + 1] += xv * w.y;
                acc[k4 * 4 + 2] += xv * w.z;
                acc[k4 * 4 + 3] += xv * w.w;
            }
        }
    }

    if (node < N) {
        float mx = acc[0];
        #pragma unroll
        for (int k = 1; k < KCL; k++) mx = fmaxf(mx, acc[k]);
        float s = 0.f;
        #pragma unroll
        for (int k = 0; k < KCL; k++) { acc[k] = expf(acc[k] - mx); s += acc[k]; }
        float inv = 1.f / s;
        float ent = 0.f;
        float dgs = g_deg_src[node];
        #pragma unroll
        for (int k = 0; k < KCL; k++) {
            acc[k] *= inv;
            ent += acc[k] * logf(acc[k] + 1e-8f);
        }
        float4* o4 = (float4*)(out + (size_t)node * KCL);
        o4[0] = make_float4(acc[0], acc[1], acc[2], acc[3]);
        o4[1] = make_float4(acc[4], acc[5], acc[6], acc[7]);
        o4[2] = make_float4(acc[8], acc[9], acc[10], acc[11]);
        o4[3] = make_float4(acc[12], acc[13], acc[14], acc[15]);
        #pragma unroll
        for (int k = 0; k < KCL; k++) {
            atomicAdd(&sred[k], acc[k]);
            atomicAdd(&sred[16 + k], dgs * acc[k]);
        }
        atomicAdd(&sred[32], ent);
    }
    __syncthreads();
    if (tid < KCL) {
        atomicAdd(&g_cs[tid], sred[tid]);
        atomicAdd(&g_dS[tid], sred[16 + tid]);
    }
    if (tid == 32) atomicAdd(&g_sc[1], sred[32]);
}

// ---------------- trace(S^T A S) = sum over edges of <a[src], a[dst]> ----------------
__global__ void trace_kernel(const float* __restrict__ assign, const int* __restrict__ src,
                             const int* __restrict__ dst, int E) {
    int e = blockIdx.x * blockDim.x + threadIdx.x;
    float t = 0.f;
    if (e < E) {
        const float4* a = (const float4*)(assign + (size_t)src[e] * KCL);
        const float4* b = (const float4*)(assign + (size_t)dst[e] * KCL);
        #pragma unroll
        for (int j = 0; j < 4; j++) {
            float4 x = a[j], y = b[j];
            t += x.x * y.x + x.y * y.y + x.z * y.z + x.w * y.w;
        }
    }
    #pragma unroll
    for (int o = 16; o; o >>= 1) t += __shfl_down_sync(0xffffffffu, t, o);
    __shared__ float sw[8];
    if ((threadIdx.x & 31) == 0) sw[threadIdx.x >> 5] = t;
    __syncthreads();
    if (threadIdx.x < 8) {
        float v = sw[threadIdx.x];
        #pragma unroll
        for (int o = 4; o; o >>= 1) v += __shfl_down_sync(0xffu, v, o);
        if (threadIdx.x == 0) atomicAdd(&g_sc[0], v);
    }
}

// ---------------- pooled_raw[k,d] += sum_i a[i,k]*emb[i,d] ----------------
__global__ void pooled_kernel(const float* __restrict__ assign, const float* __restrict__ emb,
                              float* __restrict__ pooled, int N) {
    __shared__ __align__(16) float sA[128 * KCL];
    int tid = threadIdx.x;  // 128
    int i0 = blockIdx.x * 128;
    int d = blockIdx.y * 128 + tid;
    for (int idx = tid; idx < 128 * KCL; idx += 128) {
        int gi = i0 + (idx >> 4);
        sA[idx] = (gi < N) ? assign[(size_t)gi * KCL + (idx & 15)] : 0.f;
    }
    __syncthreads();
    float acc[KCL] = {};
    int imax = min(128, N - i0);
    for (int i = 0; i < imax; i++) {
        float ev = emb[(size_t)(i0 + i) * DIM + d];
        const float4* a4 = (const float4*)&sA[i * KCL];
        #pragma unroll
        for (int k4 = 0; k4 < 4; k4++) {
            float4 a = a4[k4];
            acc[k4 * 4 + 0] += a.x * ev;
            acc[k4 * 4 + 1] += a.y * ev;
            acc[k4 * 4 + 2] += a.z * ev;
            acc[k4 * 4 + 3] += a.w * ev;
        }
    }
    #pragma unroll
    for (int k = 0; k < KCL; k++)
        atomicAdd(&pooled[k * DIM + d], acc[k]);
}

// ---------------- final: scale pooled by 1/(cs+eps), compute scalars ----------------
__global__ void final_kernel(float* __restrict__ out, int N, float m) {
    float* pooled = out + (size_t)N * KCL;
    int t = threadIdx.x;  // 512 threads == DIM
    #pragma unroll
    for (int k = 0; k < KCL; k++)
        pooled[k * DIM + t] *= 1.f / (g_cs[k] + 1e-8f);
    if (t == 0) {
        float dd = 0.f, csn = 0.f;
        #pragma unroll
        for (int k = 0; k < KCL; k++) { dd += g_dS[k] * g_dS[k]; csn += g_cs[k] * g_cs[k]; }
        float normalizer = dd / (2.f * m);
        float spectral = -(g_sc[0] - (float)KCL * normalizer) / (2.f * m);
        float collapse = sqrtf(csn) / (float)N * sqrtf((float)KCL) - 1.f;
        float entropy = -g_sc[1] / (float)N;
        float ent_loss = -0.1f * entropy;
        float total = spectral + collapse + ent_loss;
        float* s = pooled + KCL * DIM;
        s[0] = spectral;
        s[1] = collapse;
        s[2] = total;
        s[3] = ent_loss;
    }
}

// ---------------- launch ----------------
extern "C" void kernel_launch(void* const* d_in, const int* in_sizes, int n_in,
                              void* d_out, int out_size) {
    const float* emb  = (const float*)d_in[0];
    const int*   esrc = (const int*)d_in[1];
    const int*   edst = (const int*)d_in[2];
    const float* W1   = (const float*)d_in[3];
    const float* b1   = (const float*)d_in[4];
    const float* W2   = (const float*)d_in[5];
    const float* b2   = (const float*)d_in[6];
    const float* Wa   = (const float*)d_in[7];
    const float* ba   = (const float*)d_in[8];
    float* out = (float*)d_out;

    int E = in_sizes[1];
    int N = in_sizes[0] / DIM;
    float* pooled = out + (size_t)N * KCL;

    float *bufA, *bufB, *bufC;
    cudaGetSymbolAddress((void**)&bufA, g_bufA);
    cudaGetSymbolAddress((void**)&bufB, g_bufB);
    cudaGetSymbolAddress((void**)&bufC, g_bufC);

    int nb256 = (N + 255) / 256;
    int eb256 = (E + 255) / 256;
    int nh = N * HID;

    // reset accumulators (every replay)
    zero_deg_kernel<<<nb256, 256>>>(N);
    zero_misc_kernel<<<(KCL * DIM + 255) / 256, 256>>>(pooled);

    // degrees + symmetric norm
    degree_kernel<<<eb256, 256>>>(esrc, edst, E);
    dis_kernel<<<nb256, 256>>>(N);

    dim3 g1((N + 127) / 128, HID / 128);

    // ---- GCN layer 1 (GEMM writes X and dis^2*X simultaneously) ----
    sgemm128_kernel<<<g1, 256>>>(emb, W1, bufA, bufB, N, DIM, HID);
    edge_scatter_kernel<<<(E * 32 + 255) / 256, 256>>>(bufA, bufB, esrc, edst, E);
    selu_bias_kernel<<<(nh + 255) / 256, 256>>>(bufB, b1, nullptr, bufA, nh);  // bufA = x = x_skip

    // ---- GCN layer 2 ----
    sgemm128_kernel<<<g1, 256>>>(bufA, W2, bufC, bufB, N, HID, HID);
    edge_scatter_kernel<<<(E * 32 + 255) / 256, 256>>>(bufC, bufB, esrc, edst, E);
    selu_bias_kernel<<<(nh + 255) / 256, 256>>>(bufB, b2, bufA, bufC, nh);     // bufC = x2 (+skip)

    // ---- assignments + fused cs/dS/entropy reductions ----
    assign_kernel<<<(N + 127) / 128, 128>>>(bufC, Wa, ba, out, N);

    // ---- trace over edges ----
    trace_kernel<<<eb256, 256>>>(out, esrc, edst, E);

    // ---- pooled ----
    pooled_kernel<<<dim3((N + 127) / 128, DIM / 128), 128>>>(out, emb, pooled, N);

    // ---- scalars + pooled normalization ----
    final_kernel<<<1, DIM>>>(out, N, 0.5f * (float)E);
}

// round 10
// speedup vs baseline: 1.0906x; 1.0387x over previous
#include <cuda_runtime.h>
#include <cuda_bf16.h>
#include <math.h>
#include <stdint.h>

#define DIM 512
#define HID 256
#define KCL 16
#define NMAX 50000

// ---------------- scratch (device globals: alloc-free rule) ----------------
__device__ float g_bufA[NMAX * HID];   // X1 -> x_skip/x
__device__ float g_bufB[NMAX * HID];   // aggregation buffer
__device__ float g_bufC[NMAX * HID];   // X2pre -> x2
__device__ __nv_bfloat16 g_hi[NMAX * DIM];   // bf16 split of GEMM input (emb, then x)
__device__ __nv_bfloat16 g_lo[NMAX * DIM];
__device__ __nv_bfloat16 g_w1t_hi[HID * DIM];  // W1^T [256][512]
__device__ __nv_bfloat16 g_w1t_lo[HID * DIM];
__device__ __nv_bfloat16 g_w2t_hi[HID * HID];  // W2^T [256][256]
__device__ __nv_bfloat16 g_w2t_lo[HID * HID];
__device__ float g_deg_src[NMAX];
__device__ float g_deg_dst[NMAX];
__device__ float g_dis[NMAX];
__device__ float g_cs[KCL];
__device__ float g_dS[KCL];
__device__ float g_sc[2];              // [0]=trace_pooled, [1]=entropy sum

// ---------------- zero kernels ----------------
__global__ void zero_deg_kernel(int N) {
    int i = blockIdx.x * blockDim.x + threadIdx.x;
    if (i < N) { g_deg_src[i] = 0.f; g_deg_dst[i] = 0.f; }
}

__global__ void zero_misc_kernel(float* pooled) {
    int i = blockIdx.x * blockDim.x + threadIdx.x;
    if (i < KCL * DIM) pooled[i] = 0.f;
    if (i < KCL) { g_cs[i] = 0.f; g_dS[i] = 0.f; }
    if (i < 2) g_sc[i] = 0.f;
}

// ---------------- degrees ----------------
__global__ void degree_kernel(const int* __restrict__ src, const int* __restrict__ dst, int E) {
    int e = blockIdx.x * blockDim.x + threadIdx.x;
    if (e < E) {
        atomicAdd(&g_deg_src[src[e]], 1.f);
        atomicAdd(&g_deg_dst[dst[e]], 1.f);
    }
}

__global__ void dis_kernel(int N) {
    int i = blockIdx.x * blockDim.x + threadIdx.x;
    if (i < N) g_dis[i] = rsqrtf(1.f + g_deg_dst[i]);
}

// ---------------- bf16 split helpers ----------------
__global__ void split_kernel(const float* __restrict__ src, __nv_bfloat16* __restrict__ hi,
                             __nv_bfloat16* __restrict__ lo, int total) {
    int i = blockIdx.x * blockDim.x + threadIdx.x;
    if (i >= total) return;
    float f = src[i];
    __nv_bfloat16 h = __float2bfloat16(f);
    hi[i] = h;
    lo[i] = __float2bfloat16(f - __bfloat162float(h));
}

// W[K][N] -> Wt hi/lo [N][K]
__global__ void splitT_kernel(const float* __restrict__ W, __nv_bfloat16* __restrict__ thi,
                              __nv_bfloat16* __restrict__ tlo, int K, int N) {
    int idx = blockIdx.x * blockDim.x + threadIdx.x;
    if (idx >= K * N) return;
    int k = idx / N, n = idx % N;
    float f = W[idx];
    __nv_bfloat16 h = __float2bfloat16(f);
    thi[n * K + k] = h;
    tlo[n * K + k] = __float2bfloat16(f - __bfloat162float(h));
}

// ---------------- mma helper ----------------
__device__ __forceinline__ void mma16816(float& c0, float& c1, float& c2, float& c3,
                                         uint32_t a0, uint32_t a1, uint32_t a2, uint32_t a3,
                                         uint32_t b0, uint32_t b1) {
    asm volatile("mma.sync.aligned.m16n8k16.row.col.f32.bf16.bf16.f32 "
                 "{%0,%1,%2,%3}, {%4,%5,%6,%7}, {%8,%9}, {%0,%1,%2,%3};"
                 : "+f"(c0), "+f"(c1), "+f"(c2), "+f"(c3)
                 : "r"(a0), "r"(a1), "r"(a2), "r"(a3), "r"(b0), "r"(b1));
}

// ---------------- bf16x3-split tensor-core GEMM ----------------
// C[M,Nd] = A[M,K] @ Bt[Nd,K]^T with A,Bt in (hi,lo) bf16 splits; fp32 accum.
// Also writes AGG = dis[row]^2 * C (fused self-loop init) when AGG != null.
// Block: 128x128 tile, 256 threads (8 warps = 2m x 4n of 64x32 warp tiles), BK=32.
#define SPAD 40
__global__ __launch_bounds__(256, 1)
void mma_gemm_kernel(const __nv_bfloat16* __restrict__ Ahi, const __nv_bfloat16* __restrict__ Alo,
                     const __nv_bfloat16* __restrict__ Bthi, const __nv_bfloat16* __restrict__ Btlo,
                     float* __restrict__ C, float* __restrict__ AGG,
                     int M, int K, int Nd) {
    __shared__ __align__(8) __nv_bfloat16 As[2][128][SPAD];  // [hi/lo][m][k]
    __shared__ __align__(8) __nv_bfloat16 Bs[2][128][SPAD];  // [hi/lo][n][k]
    int tid = threadIdx.x;
    int lane = tid & 31, wid = tid >> 5;
    int wm = wid & 1, wn = wid >> 1;         // warp grid 2 x 4
    int row0 = blockIdx.x * 128;
    int col0 = blockIdx.y * 128;
    int qr = lane >> 2, qk = (lane & 3) * 2;

    float acc[4][4][4] = {};

    for (int k0 = 0; k0 < K; k0 += 32) {
        __syncthreads();
        // load A tile: 128 rows x 32 k, hi+lo, via uint2 (4 bf16)
        #pragma unroll
        for (int it = 0; it < 4; it++) {
            int idx = tid + it * 256;        // 0..1023
            int r = idx >> 3, seg = idx & 7; // 8 uint2 per row
            int grow = row0 + r;
            uint2 vh = make_uint2(0u, 0u), vl = make_uint2(0u, 0u);
            if (grow < M) {
                vh = *(const uint2*)(Ahi + (size_t)grow * K + k0 + seg * 4);
                vl = *(const uint2*)(Alo + (size_t)grow * K + k0 + seg * 4);
            }
            *(uint2*)&As[0][r][seg * 4] = vh;
            *(uint2*)&As[1][r][seg * 4] = vl;
        }
        // load B tile: 128 cols (rows of Bt) x 32 k
        #pragma unroll
        for (int it = 0; it < 4; it++) {
            int idx = tid + it * 256;
            int r = idx >> 3, seg = idx & 7;
            int gcol = col0 + r;
            *(uint2*)&Bs[0][r][seg * 4] = *(const uint2*)(Bthi + (size_t)gcol * K + k0 + seg * 4);
            *(uint2*)&Bs[1][r][seg * 4] = *(const uint2*)(Btlo + (size_t)gcol * K + k0 + seg * 4);
        }
        __syncthreads();

        #pragma unroll
        for (int kk = 0; kk < 32; kk += 16) {
            uint32_t ah[4][4], al[4][4], bh[4][2], bl[4][2];
            #pragma unroll
            for (int mt = 0; mt < 4; mt++) {
                int m = wm * 64 + mt * 16;
                ah[mt][0] = *(const uint32_t*)&As[0][m + qr][kk + qk];
                ah[mt][1] = *(const uint32_t*)&As[0][m + qr + 8][kk + qk];
                ah[mt][2] = *(const uint32_t*)&As[0][m + qr][kk + qk + 8];
                ah[mt][3] = *(const uint32_t*)&As[0][m + qr + 8][kk + qk + 8];
                al[mt][0] = *(const uint32_t*)&As[1][m + qr][kk + qk];
                al[mt][1] = *(const uint32_t*)&As[1][m + qr + 8][kk + qk];
                al[mt][2] = *(const uint32_t*)&As[1][m + qr][kk + qk + 8];
                al[mt][3] = *(const uint32_t*)&As[1][m + qr + 8][kk + qk + 8];
            }
            #pragma unroll
            for (int nt = 0; nt < 4; nt++) {
                int n = wn * 32 + nt * 8;
                bh[nt][0] = *(const uint32_t*)&Bs[0][n + qr][kk + qk];
                bh[nt][1] = *(const uint32_t*)&Bs[0][n + qr][kk + qk + 8];
                bl[nt][0] = *(const uint32_t*)&Bs[1][n + qr][kk + qk];
                bl[nt][1] = *(const uint32_t*)&Bs[1][n + qr][kk + qk + 8];
            }
            #pragma unroll
            for (int mt = 0; mt < 4; mt++)
                #pragma unroll
                for (int nt = 0; nt < 4; nt++) {
                    float* c = acc[mt][nt];
                    mma16816(c[0], c[1], c[2], c[3],
                             ah[mt][0], ah[mt][1], ah[mt][2], ah[mt][3], bh[nt][0], bh[nt][1]);
                    mma16816(c[0], c[1], c[2], c[3],
                             ah[mt][0], ah[mt][1], ah[mt][2], ah[mt][3], bl[nt][0], bl[nt][1]);
                    mma16816(c[0], c[1], c[2], c[3],
                             al[mt][0], al[mt][1], al[mt][2], al[mt][3], bh[nt][0], bh[nt][1]);
                }
        }
    }

    // epilogue
    #pragma unroll
    for (int mt = 0; mt < 4; mt++) {
        #pragma unroll
        for (int half = 0; half < 2; half++) {
            int row = row0 + wm * 64 + mt * 16 + qr + half * 8;
            if (row >= M) continue;
            float dv = g_dis[row];
            float d2 = dv * dv;
            float* crow = C + (size_t)row * Nd;
            float* grow = (AGG != nullptr) ? (AGG + (size_t)row * Nd) : nullptr;
            #pragma unroll
            for (int nt = 0; nt < 4; nt++) {
                int col = col0 + wn * 32 + nt * 8 + (lane & 3) * 2;
                float v0 = acc[mt][nt][half * 2 + 0];
                float v1 = acc[mt][nt][half * 2 + 1];
                crow[col] = v0;
                crow[col + 1] = v1;
                if (grow) {
                    grow[col] = v0 * d2;
                    grow[col + 1] = v1 * d2;
                }
            }
        }
    }
}

// ---------------- edge scatter: AGG[dst] += X[src] * dis[src]*dis[dst] ----------------
// warp per edge, scalar atomicAdd (proven-stable path)
__global__ void edge_scatter_kernel(const float* __restrict__ X, float* __restrict__ AGG,
                                    const int* __restrict__ src, const int* __restrict__ dst, int E) {
    int g = blockIdx.x * blockDim.x + threadIdx.x;
    int e = g >> 5, lane = g & 31;
    if (e >= E) return;
    int s = src[e], d = dst[e];
    float nrm = g_dis[s] * g_dis[d];
    const float4* xs = (const float4*)(X + (size_t)s * HID);
    float* ag = AGG + (size_t)d * HID;
    #pragma unroll
    for (int j = 0; j < 2; j++) {
        int q = lane + 32 * j;
        float4 v = xs[q];
        int c = q * 4;
        atomicAdd(ag + c + 0, v.x * nrm);
        atomicAdd(ag + c + 1, v.y * nrm);
        atomicAdd(ag + c + 2, v.z * nrm);
        atomicAdd(ag + c + 3, v.w * nrm);
    }
}

// ---------------- bias + SELU (+ optional skip, + optional bf16 split out) ----------------
__global__ void selu_bias_kernel(const float* __restrict__ AGG, const float* __restrict__ b,
                                 const float* __restrict__ skip, float* __restrict__ out,
                                 __nv_bfloat16* __restrict__ ohi, __nv_bfloat16* __restrict__ olo,
                                 int total) {
    int idx = blockIdx.x * blockDim.x + threadIdx.x;
    if (idx >= total) return;
    const float alpha = 1.6732632423543772f;
    const float scale = 1.0507009873554805f;
    float v = AGG[idx] + b[idx & (HID - 1)];
    v = (v > 0.f) ? scale * v : scale * alpha * (expf(v) - 1.f);
    if (skip != nullptr) v += skip[idx];
    out[idx] = v;
    if (ohi != nullptr) {
        __nv_bfloat16 h = __float2bfloat16(v);
        ohi[idx] = h;
        olo[idx] = __float2bfloat16(v - __bfloat162float(h));
    }
}

// ---------------- logits -> softmax -> assignments + fused reductions ----------------
__global__ void assign_kernel(const float* __restrict__ X, const float* __restrict__ Wa,
                              const float* __restrict__ ba, float* __restrict__ out, int N) {
    __shared__ __align__(16) float sWa[HID * KCL];
    __shared__ __align__(16) float sX[128 * 33];
    __shared__ float sred[33];
    int tid = threadIdx.x;
    for (int i = tid; i < HID * KCL; i += 128) sWa[i] = Wa[i];
    if (tid < 33) sred[tid] = 0.f;
    int node = blockIdx.x * 128 + tid;
    float acc[KCL];
    #pragma unroll
    for (int k = 0; k < KCL; k++) acc[k] = ba[k];

    for (int cb = 0; cb < HID; cb += 32) {
        __syncthreads();
        for (int idx = tid; idx < 128 * 32; idx += 128) {
            int ln = idx >> 5, c = idx & 31;
            int gn = blockIdx.x * 128 + ln;
            sX[ln * 33 + c] = (gn < N) ? X[(size_t)gn * HID + cb + c] : 0.f;
        }
        __syncthreads();
        #pragma unroll
        for (int cc = 0; cc < 32; cc++) {
            float xv = sX[tid * 33 + cc];
            const float4* w4 = (const float4*)&sWa[(cb + cc) * KCL];
            #pragma unroll
            for (int k4 = 0; k4 < 4; k4++) {
                float4 w = w4[k4];
                acc[k4 * 4 + 0] += xv * w.x;
                acc[k4 * 4 + 1] += xv * w.y;
                acc[k4 * 4 + 2] += xv * w.z;
                acc[k4 * 4 + 3] += xv * w.w;
            }
        }
    }

    if (node < N) {
        float mx = acc[0];
        #pragma unroll
        for (int k = 1; k < KCL; k++) mx = fmaxf(mx, acc[k]);
        float s = 0.f;
        #pragma unroll
        for (int k = 0; k < KCL; k++) { acc[k] = expf(acc[k] - mx); s += acc[k]; }
        float inv = 1.f / s;
        float ent = 0.f;
        float dgs = g_deg_src[node];
        #pragma unroll
        for (int k = 0; k < KCL; k++) {
            acc[k] *= inv;
            ent += acc[k] * logf(acc[k] + 1e-8f);
        }
        float4* o4 = (float4*)(out + (size_t)node * KCL);
        o4[0] = make_float4(acc[0], acc[1], acc[2], acc[3]);
        o4[1] = make_float4(acc[4], acc[5], acc[6], acc[7]);
        o4[2] = make_float4(acc[8], acc[9], acc[10], acc[11]);
        o4[3] = make_float4(acc[12], acc[13], acc[14], acc[15]);
        #pragma unroll
        for (int k = 0; k < KCL; k++) {
            atomicAdd(&sred[k], acc[k]);
            atomicAdd(&sred[16 + k], dgs * acc[k]);
        }
        atomicAdd(&sred[32], ent);
    }
    __syncthreads();
    if (tid < KCL) {
        atomicAdd(&g_cs[tid], sred[tid]);
        atomicAdd(&g_dS[tid], sred[16 + tid]);
    }
    if (tid == 32) atomicAdd(&g_sc[1], sred[32]);
}

// ---------------- trace(S^T A S) = sum over edges of <a[src], a[dst]> ----------------
__global__ void trace_kernel(const float* __restrict__ assign, const int* __restrict__ src,
                             const int* __restrict__ dst, int E) {
    int e = blockIdx.x * blockDim.x + threadIdx.x;
    float t = 0.f;
    if (e < E) {
        const float4* a = (const float4*)(assign + (size_t)src[e] * KCL);
        const float4* b = (const float4*)(assign + (size_t)dst[e] * KCL);
        #pragma unroll
        for (int j = 0; j < 4; j++) {
            float4 x = a[j], y = b[j];
            t += x.x * y.x + x.y * y.y + x.z * y.z + x.w * y.w;
        }
    }
    #pragma unroll
    for (int o = 16; o; o >>= 1) t += __shfl_down_sync(0xffffffffu, t, o);
    __shared__ float sw[8];
    if ((threadIdx.x & 31) == 0) sw[threadIdx.x >> 5] = t;
    __syncthreads();
    if (threadIdx.x < 8) {
        float v = sw[threadIdx.x];
        #pragma unroll
        for (int o = 4; o; o >>= 1) v += __shfl_down_sync(0xffu, v, o);
        if (threadIdx.x == 0) atomicAdd(&g_sc[0], v);
    }
}

// ---------------- pooled_raw[k,d] += sum_i a[i,k]*emb[i,d] ----------------
__global__ void pooled_kernel(const float* __restrict__ assign, const float* __restrict__ emb,
                              float* __restrict__ pooled, int N) {
    __shared__ __align__(16) float sA[128 * KCL];
    int tid = threadIdx.x;  // 128
    int i0 = blockIdx.x * 128;
    int d = blockIdx.y * 128 + tid;
    for (int idx = tid; idx < 128 * KCL; idx += 128) {
        int gi = i0 + (idx >> 4);
        sA[idx] = (gi < N) ? assign[(size_t)gi * KCL + (idx & 15)] : 0.f;
    }
    __syncthreads();
    float acc[KCL] = {};
    int imax = min(128, N - i0);
    for (int i = 0; i < imax; i++) {
        float ev = emb[(size_t)(i0 + i) * DIM + d];
        const float4* a4 = (const float4*)&sA[i * KCL];
        #pragma unroll
        for (int k4 = 0; k4 < 4; k4++) {
            float4 a = a4[k4];
            acc[k4 * 4 + 0] += a.x * ev;
            acc[k4 * 4 + 1] += a.y * ev;
            acc[k4 * 4 + 2] += a.z * ev;
            acc[k4 * 4 + 3] += a.w * ev;
        }
    }
    #pragma unroll
    for (int k = 0; k < KCL; k++)
        atomicAdd(&pooled[k * DIM + d], acc[k]);
}

// ---------------- final: scale pooled by 1/(cs+eps), compute scalars ----------------
__global__ void final_kernel(float* __restrict__ out, int N, float m) {
    float* pooled = out + (size_t)N * KCL;
    int t = threadIdx.x;  // 512 threads == DIM
    #pragma unroll
    for (int k = 0; k < KCL; k++)
        pooled[k * DIM + t] *= 1.f / (g_cs[k] + 1e-8f);
    if (t == 0) {
        float dd = 0.f, csn = 0.f;
        #pragma unroll
        for (int k = 0; k < KCL; k++) { dd += g_dS[k] * g_dS[k]; csn += g_cs[k] * g_cs[k]; }
        float normalizer = dd / (2.f * m);
        float spectral = -(g_sc[0] - (float)KCL * normalizer) / (2.f * m);
        float collapse = sqrtf(csn) / (float)N * sqrtf((float)KCL) - 1.f;
        float entropy = -g_sc[1] / (float)N;
        float ent_loss = -0.1f * entropy;
        float total = spectral + collapse + ent_loss;
        float* s = pooled + KCL * DIM;
        s[0] = spectral;
        s[1] = collapse;
        s[2] = total;
        s[3] = ent_loss;
    }
}

// ---------------- launch ----------------
extern "C" void kernel_launch(void* const* d_in, const int* in_sizes, int n_in,
                              void* d_out, int out_size) {
    const float* emb  = (const float*)d_in[0];
    const int*   esrc = (const int*)d_in[1];
    const int*   edst = (const int*)d_in[2];
    const float* W1   = (const float*)d_in[3];
    const float* b1   = (const float*)d_in[4];
    const float* W2   = (const float*)d_in[5];
    const float* b2   = (const float*)d_in[6];
    const float* Wa   = (const float*)d_in[7];
    const float* ba   = (const float*)d_in[8];
    float* out = (float*)d_out;

    int E = in_sizes[1];
    int N = in_sizes[0] / DIM;
    float* pooled = out + (size_t)N * KCL;

    float *bufA, *bufB, *bufC;
    __nv_bfloat16 *hi, *lo, *w1thi, *w1tlo, *w2thi, *w2tlo;
    cudaGetSymbolAddress((void**)&bufA, g_bufA);
    cudaGetSymbolAddress((void**)&bufB, g_bufB);
    cudaGetSymbolAddress((void**)&bufC, g_bufC);
    cudaGetSymbolAddress((void**)&hi, g_hi);
    cudaGetSymbolAddress((void**)&lo, g_lo);
    cudaGetSymbolAddress((void**)&w1thi, g_w1t_hi);
    cudaGetSymbolAddress((void**)&w1tlo, g_w1t_lo);
    cudaGetSymbolAddress((void**)&w2thi, g_w2t_hi);
    cudaGetSymbolAddress((void**)&w2tlo, g_w2t_lo);

    int nb256 = (N + 255) / 256;
    int eb256 = (E + 255) / 256;
    int nh = N * HID;

    // reset accumulators (every replay)
    zero_deg_kernel<<<nb256, 256>>>(N);
    zero_misc_kernel<<<(KCL * DIM + 255) / 256, 256>>>(pooled);

    // degrees + symmetric norm
    degree_kernel<<<eb256, 256>>>(esrc, edst, E);
    dis_kernel<<<nb256, 256>>>(N);

    // bf16 splits: emb and both weight matrices (transposed)
    split_kernel<<<(N * DIM + 255) / 256, 256>>>(emb, hi, lo, N * DIM);
    splitT_kernel<<<(DIM * HID + 255) / 256, 256>>>(W1, w1thi, w1tlo, DIM, HID);
    splitT_kernel<<<(HID * HID + 255) / 256, 256>>>(W2, w2thi, w2tlo, HID, HID);

    dim3 g1((N + 127) / 128, HID / 128);

    // ---- GCN layer 1 (tensor-core GEMM writes X and dis^2*X simultaneously) ----
    mma_gemm_kernel<<<g1, 256>>>(hi, lo, w1thi, w1tlo, bufA, bufB, N, DIM, HID);
    edge_scatter_kernel<<<(E * 32 + 255) / 256, 256>>>(bufA, bufB, esrc, edst, E);
    // selu -> bufA (fp32 x/x_skip) + bf16 splits into hi/lo (GEMM2 input, lda=HID)
    selu_bias_kernel<<<(nh + 255) / 256, 256>>>(bufB, b1, nullptr, bufA, hi, lo, nh);

    // ---- GCN layer 2 ----
    mma_gemm_kernel<<<g1, 256>>>(hi, lo, w2thi, w2tlo, bufC, bufB, N, HID, HID);
    edge_scatter_kernel<<<(E * 32 + 255) / 256, 256>>>(bufC, bufB, esrc, edst, E);
    selu_bias_kernel<<<(nh + 255) / 256, 256>>>(bufB, b2, bufA, bufC, nullptr, nullptr, nh);

    // ---- assignments + fused cs/dS/entropy reductions ----
    assign_kernel<<<(N + 127) / 128, 128>>>(bufC, Wa, ba, out, N);

    // ---- trace over edges ----
    trace_kernel<<<eb256, 256>>>(out, esrc, edst, E);

    // ---- pooled ----
    pooled_kernel<<<dim3((N + 127) / 128, DIM / 128), 128>>>(out, emb, pooled, N);

    // ---- scalars + pooled normalization ----
    final_kernel<<<1, DIM>>>(out, N, 0.5f * (float)E);
}

// round 11
// speedup vs baseline: 2.3221x; 2.1291x over previous
#include <cuda_runtime.h>
#include <cuda_bf16.h>
#include <math.h>
#include <stdint.h>

#define DIM 512
#define HID 256
#define KCL 16
#define NMAX 50000
#define EMAX 800000

// ---------------- scratch (device globals: alloc-free rule) ----------------
__device__ float g_bufA[NMAX * HID];   // GEMM outputs
__device__ float g_bufB[NMAX * HID];   // x (= x_skip) after layer-1 gather
__device__ float g_bufC[NMAX * HID];   // x2 after layer-2 gather
__device__ __nv_bfloat16 g_hi[NMAX * DIM];
__device__ __nv_bfloat16 g_lo[NMAX * DIM];
__device__ __nv_bfloat16 g_w1t_hi[HID * DIM];
__device__ __nv_bfloat16 g_w1t_lo[HID * DIM];
__device__ __nv_bfloat16 g_w2t_hi[HID * HID];
__device__ __nv_bfloat16 g_w2t_lo[HID * HID];
__device__ int   g_degi_src[NMAX];
__device__ int   g_degi_dst[NMAX];
__device__ int   g_rowoff[NMAX];
__device__ int   g_cursor[NMAX];
__device__ int   g_part[256];
__device__ int   g_csr[EMAX];
__device__ float g_deg_src[NMAX];
__device__ float g_dis[NMAX];
__device__ float g_cs[KCL];
__device__ float g_dS[KCL];
__device__ float g_sc[2];              // [0]=trace, [1]=entropy

__device__ __forceinline__ float selu_f(float v) {
    const float alpha = 1.6732632423543772f;
    const float scale = 1.0507009873554805f;
    return (v > 0.f) ? scale * v : scale * alpha * (expf(v) - 1.f);
}

// ---------------- bf16 split helpers ----------------
__global__ void split_kernel(const float* __restrict__ src, __nv_bfloat16* __restrict__ hi,
                             __nv_bfloat16* __restrict__ lo, int total) {
    int i = blockIdx.x * blockDim.x + threadIdx.x;
    if (i >= total) return;
    float f = src[i];
    __nv_bfloat16 h = __float2bfloat16(f);
    hi[i] = h;
    lo[i] = __float2bfloat16(f - __bfloat162float(h));
}

// W[K][N] -> Wt hi/lo [N][K]
__global__ void splitT_kernel(const float* __restrict__ W, __nv_bfloat16* __restrict__ thi,
                              __nv_bfloat16* __restrict__ tlo, int K, int N) {
    int idx = blockIdx.x * blockDim.x + threadIdx.x;
    if (idx >= K * N) return;
    int k = idx / N, n = idx % N;
    float f = W[idx];
    __nv_bfloat16 h = __float2bfloat16(f);
    thi[n * K + k] = h;
    tlo[n * K + k] = __float2bfloat16(f - __bfloat162float(h));
}

// ---------------- mma helper ----------------
__device__ __forceinline__ void mma16816(float& c0, float& c1, float& c2, float& c3,
                                         uint32_t a0, uint32_t a1, uint32_t a2, uint32_t a3,
                                         uint32_t b0, uint32_t b1) {
    asm volatile("mma.sync.aligned.m16n8k16.row.col.f32.bf16.bf16.f32 "
                 "{%0,%1,%2,%3}, {%4,%5,%6,%7}, {%8,%9}, {%0,%1,%2,%3};"
                 : "+f"(c0), "+f"(c1), "+f"(c2), "+f"(c3)
                 : "r"(a0), "r"(a1), "r"(a2), "r"(a3), "r"(b0), "r"(b1));
}

// ---------------- bf16x3-split tensor-core GEMM (proven round-10) ----------------
#define SPAD 40
__global__ __launch_bounds__(256, 1)
void mma_gemm_kernel(const __nv_bfloat16* __restrict__ Ahi, const __nv_bfloat16* __restrict__ Alo,
                     const __nv_bfloat16* __restrict__ Bthi, const __nv_bfloat16* __restrict__ Btlo,
                     float* __restrict__ C, int M, int K, int Nd) {
    __shared__ __align__(8) __nv_bfloat16 As[2][128][SPAD];
    __shared__ __align__(8) __nv_bfloat16 Bs[2][128][SPAD];
    int tid = threadIdx.x;
    int lane = tid & 31, wid = tid >> 5;
    int wm = wid & 1, wn = wid >> 1;
    int row0 = blockIdx.x * 128;
    int col0 = blockIdx.y * 128;
    int qr = lane >> 2, qk = (lane & 3) * 2;

    float acc[4][4][4] = {};

    for (int k0 = 0; k0 < K; k0 += 32) {
        __syncthreads();
        #pragma unroll
        for (int it = 0; it < 4; it++) {
            int idx = tid + it * 256;
            int r = idx >> 3, seg = idx & 7;
            int grow = row0 + r;
            uint2 vh = make_uint2(0u, 0u), vl = make_uint2(0u, 0u);
            if (grow < M) {
                vh = *(const uint2*)(Ahi + (size_t)grow * K + k0 + seg * 4);
                vl = *(const uint2*)(Alo + (size_t)grow * K + k0 + seg * 4);
            }
            *(uint2*)&As[0][r][seg * 4] = vh;
            *(uint2*)&As[1][r][seg * 4] = vl;
        }
        #pragma unroll
        for (int it = 0; it < 4; it++) {
            int idx = tid + it * 256;
            int r = idx >> 3, seg = idx & 7;
            int gcol = col0 + r;
            *(uint2*)&Bs[0][r][seg * 4] = *(const uint2*)(Bthi + (size_t)gcol * K + k0 + seg * 4);
            *(uint2*)&Bs[1][r][seg * 4] = *(const uint2*)(Btlo + (size_t)gcol * K + k0 + seg * 4);
        }
        __syncthreads();

        #pragma unroll
        for (int kk = 0; kk < 32; kk += 16) {
            uint32_t ah[4][4], al[4][4], bh[4][2], bl[4][2];
            #pragma unroll
            for (int mt = 0; mt < 4; mt++) {
                int m = wm * 64 + mt * 16;
                ah[mt][0] = *(const uint32_t*)&As[0][m + qr][kk + qk];
                ah[mt][1] = *(const uint32_t*)&As[0][m + qr + 8][kk + qk];
                ah[mt][2] = *(const uint32_t*)&As[0][m + qr][kk + qk + 8];
                ah[mt][3] = *(const uint32_t*)&As[0][m + qr + 8][kk + qk + 8];
                al[mt][0] = *(const uint32_t*)&As[1][m + qr][kk + qk];
                al[mt][1] = *(const uint32_t*)&As[1][m + qr + 8][kk + qk];
                al[mt][2] = *(const uint32_t*)&As[1][m + qr][kk + qk + 8];
                al[mt][3] = *(const uint32_t*)&As[1][m + qr + 8][kk + qk + 8];
            }
            #pragma unroll
            for (int nt = 0; nt < 4; nt++) {
                int n = wn * 32 + nt * 8;
                bh[nt][0] = *(const uint32_t*)&Bs[0][n + qr][kk + qk];
                bh[nt][1] = *(const uint32_t*)&Bs[0][n + qr][kk + qk + 8];
                bl[nt][0] = *(const uint32_t*)&Bs[1][n + qr][kk + qk];
                bl[nt][1] = *(const uint32_t*)&Bs[1][n + qr][kk + qk + 8];
            }
            #pragma unroll
            for (int mt = 0; mt < 4; mt++)
                #pragma unroll
                for (int nt = 0; nt < 4; nt++) {
                    float* c = acc[mt][nt];
                    mma16816(c[0], c[1], c[2], c[3],
                             ah[mt][0], ah[mt][1], ah[mt][2], ah[mt][3], bh[nt][0], bh[nt][1]);
                    mma16816(c[0], c[1], c[2], c[3],
                             ah[mt][0], ah[mt][1], ah[mt][2], ah[mt][3], bl[nt][0], bl[nt][1]);
                    mma16816(c[0], c[1], c[2], c[3],
                             al[mt][0], al[mt][1], al[mt][2], al[mt][3], bh[nt][0], bh[nt][1]);
                }
        }
    }

    #pragma unroll
    for (int mt = 0; mt < 4; mt++) {
        #pragma unroll
        for (int half = 0; half < 2; half++) {
            int row = row0 + wm * 64 + mt * 16 + qr + half * 8;
            if (row >= M) continue;
            float* crow = C + (size_t)row * Nd;
            #pragma unroll
            for (int nt = 0; nt < 4; nt++) {
                int col = col0 + wn * 32 + nt * 8 + (lane & 3) * 2;
                crow[col] = acc[mt][nt][half * 2 + 0];
                crow[col + 1] = acc[mt][nt][half * 2 + 1];
            }
        }
    }
}

// ---------------- zero + degrees + CSR build ----------------
__global__ void zero_kernel(float* pooled, int N) {
    int i = blockIdx.x * blockDim.x + threadIdx.x;
    if (i < N) { g_degi_src[i] = 0; g_degi_dst[i] = 0; }
    if (i < KCL * DIM) pooled[i] = 0.f;
    if (i < KCL) { g_cs[i] = 0.f; g_dS[i] = 0.f; }
    if (i < 2) g_sc[i] = 0.f;
}

__global__ void degree_kernel(const int* __restrict__ src, const int* __restrict__ dst, int E) {
    int e = blockIdx.x * blockDim.x + threadIdx.x;
    if (e < E) {
        atomicAdd(&g_degi_src[src[e]], 1);
        atomicAdd(&g_degi_dst[dst[e]], 1);
    }
}

__global__ void scanA_kernel(int N) {
    __shared__ int s[256];
    int i = blockIdx.x * 256 + threadIdx.x;
    int v = (i < N) ? g_degi_dst[i] : 0;
    s[threadIdx.x] = v;
    __syncthreads();
    #pragma unroll
    for (int o = 1; o < 256; o <<= 1) {
        int t = (threadIdx.x >= o) ? s[threadIdx.x - o] : 0;
        __syncthreads();
        s[threadIdx.x] += t;
        __syncthreads();
    }
    if (i < N) g_rowoff[i] = s[threadIdx.x] - v;   // exclusive
    if (threadIdx.x == 255) g_part[blockIdx.x] = s[255];
}

__global__ void scanB_kernel(int nb) {
    __shared__ int s[256];
    int v = (threadIdx.x < nb) ? g_part[threadIdx.x] : 0;
    s[threadIdx.x] = v;
    __syncthreads();
    #pragma unroll
    for (int o = 1; o < 256; o <<= 1) {
        int t = (threadIdx.x >= o) ? s[threadIdx.x - o] : 0;
        __syncthreads();
        s[threadIdx.x] += t;
        __syncthreads();
    }
    if (threadIdx.x < nb) g_part[threadIdx.x] = s[threadIdx.x] - v;  // exclusive
}

__global__ void scanC_kernel(int N) {
    int i = blockIdx.x * 256 + threadIdx.x;
    if (i < N) {
        int r = g_rowoff[i] + g_part[blockIdx.x];
        g_rowoff[i] = r;
        g_cursor[i] = r;
    }
}

__global__ void fill_kernel(const int* __restrict__ src, const int* __restrict__ dst, int E) {
    int e = blockIdx.x * blockDim.x + threadIdx.x;
    if (e >= E) return;
    int pos = atomicAdd(&g_cursor[dst[e]], 1);
    g_csr[pos] = src[e];
}

__global__ void dis_kernel(int N) {
    int i = blockIdx.x * blockDim.x + threadIdx.x;
    if (i < N) {
        g_dis[i] = rsqrtf(1.f + (float)g_degi_dst[i]);
        g_deg_src[i] = (float)g_degi_src[i];
    }
}

// ---------------- CSR gather aggregation + bias + SELU (+skip, +bf16 split) ----------------
__global__ __launch_bounds__(256)
void gather_kernel(const float* __restrict__ X, const float* __restrict__ bias,
                   const float* __restrict__ skip, float* __restrict__ out,
                   __nv_bfloat16* __restrict__ ohi, __nv_bfloat16* __restrict__ olo, int N) {
    int w = (blockIdx.x * blockDim.x + threadIdx.x) >> 5;
    int lane = threadIdx.x & 31;
    if (w >= N) return;
    float dd = g_dis[w];
    float d2 = dd * dd;
    const float4* xs = (const float4*)(X + (size_t)w * HID);
    float4 s0 = xs[lane], s1 = xs[lane + 32];
    float a0x = s0.x * d2, a0y = s0.y * d2, a0z = s0.z * d2, a0w = s0.w * d2;
    float a1x = s1.x * d2, a1y = s1.y * d2, a1z = s1.z * d2, a1w = s1.w * d2;

    int start = g_rowoff[w];
    int cnt = g_degi_dst[w];
    for (int i = 0; i < cnt; i++) {
        int s = __ldg(&g_csr[start + i]);
        float c = g_dis[s] * dd;
        const float4* xr = (const float4*)(X + (size_t)s * HID);
        float4 v0 = xr[lane], v1 = xr[lane + 32];
        a0x += c * v0.x; a0y += c * v0.y; a0z += c * v0.z; a0w += c * v0.w;
        a1x += c * v1.x; a1y += c * v1.y; a1z += c * v1.z; a1w += c * v1.w;
    }

    const float4* b4 = (const float4*)bias;
    float4 b0 = b4[lane], b1 = b4[lane + 32];
    a0x = selu_f(a0x + b0.x); a0y = selu_f(a0y + b0.y);
    a0z = selu_f(a0z + b0.z); a0w = selu_f(a0w + b0.w);
    a1x = selu_f(a1x + b1.x); a1y = selu_f(a1y + b1.y);
    a1z = selu_f(a1z + b1.z); a1w = selu_f(a1w + b1.w);

    if (skip != nullptr) {
        const float4* k4 = (const float4*)(skip + (size_t)w * HID);
        float4 k0 = k4[lane], k1 = k4[lane + 32];
        a0x += k0.x; a0y += k0.y; a0z += k0.z; a0w += k0.w;
        a1x += k1.x; a1y += k1.y; a1z += k1.z; a1w += k1.w;
    }

    float4* o4 = (float4*)(out + (size_t)w * HID);
    o4[lane] = make_float4(a0x, a0y, a0z, a0w);
    o4[lane + 32] = make_float4(a1x, a1y, a1z, a1w);

    if (ohi != nullptr) {
        float f[8] = {a0x, a0y, a0z, a0w, a1x, a1y, a1z, a1w};
        __nv_bfloat16 h[8], l[8];
        #pragma unroll
        for (int j = 0; j < 8; j++) {
            h[j] = __float2bfloat16(f[j]);
            l[j] = __float2bfloat16(f[j] - __bfloat162float(h[j]));
        }
        uint2* hp = (uint2*)(ohi + (size_t)w * HID);
        uint2* lp = (uint2*)(olo + (size_t)w * HID);
        hp[lane] = *(uint2*)&h[0];
        hp[lane + 32] = *(uint2*)&h[4];
        lp[lane] = *(uint2*)&l[0];
        lp[lane + 32] = *(uint2*)&l[4];
    }
}

// ---------------- logits -> softmax -> assignments + fused reductions ----------------
__global__ void assign_kernel(const float* __restrict__ X, const float* __restrict__ Wa,
                              const float* __restrict__ ba, float* __restrict__ out, int N) {
    __shared__ __align__(16) float sWa[HID * KCL];
    __shared__ __align__(16) float sX[128 * 33];
    __shared__ float sred[33];
    int tid = threadIdx.x;
    for (int i = tid; i < HID * KCL; i += 128) sWa[i] = Wa[i];
    if (tid < 33) sred[tid] = 0.f;
    int node = blockIdx.x * 128 + tid;
    float acc[KCL];
    #pragma unroll
    for (int k = 0; k < KCL; k++) acc[k] = ba[k];

    for (int cb = 0; cb < HID; cb += 32) {
        __syncthreads();
        for (int idx = tid; idx < 128 * 32; idx += 128) {
            int ln = idx >> 5, c = idx & 31;
            int gn = blockIdx.x * 128 + ln;
            sX[ln * 33 + c] = (gn < N) ? X[(size_t)gn * HID + cb + c] : 0.f;
        }
        __syncthreads();
        #pragma unroll
        for (int cc = 0; cc < 32; cc++) {
            float xv = sX[tid * 33 + cc];
            const float4* w4 = (const float4*)&sWa[(cb + cc) * KCL];
            #pragma unroll
            for (int k4 = 0; k4 < 4; k4++) {
                float4 w = w4[k4];
                acc[k4 * 4 + 0] += xv * w.x;
                acc[k4 * 4 + 1] += xv * w.y;
                acc[k4 * 4 + 2] += xv * w.z;
                acc[k4 * 4 + 3] += xv * w.w;
            }
        }
    }

    if (node < N) {
        float mx = acc[0];
        #pragma unroll
        for (int k = 1; k < KCL; k++) mx = fmaxf(mx, acc[k]);
        float s = 0.f;
        #pragma unroll
        for (int k = 0; k < KCL; k++) { acc[k] = expf(acc[k] - mx); s += acc[k]; }
        float inv = 1.f / s;
        float ent = 0.f;
        float dgs = g_deg_src[node];
        #pragma unroll
        for (int k = 0; k < KCL; k++) {
            acc[k] *= inv;
            ent += acc[k] * logf(acc[k] + 1e-8f);
        }
        float4* o4 = (float4*)(out + (size_t)node * KCL);
        o4[0] = make_float4(acc[0], acc[1], acc[2], acc[3]);
        o4[1] = make_float4(acc[4], acc[5], acc[6], acc[7]);
        o4[2] = make_float4(acc[8], acc[9], acc[10], acc[11]);
        o4[3] = make_float4(acc[12], acc[13], acc[14], acc[15]);
        #pragma unroll
        for (int k = 0; k < KCL; k++) {
            atomicAdd(&sred[k], acc[k]);
            atomicAdd(&sred[16 + k], dgs * acc[k]);
        }
        atomicAdd(&sred[32], ent);
    }
    __syncthreads();
    if (tid < KCL) {
        atomicAdd(&g_cs[tid], sred[tid]);
        atomicAdd(&g_dS[tid], sred[16 + tid]);
    }
    if (tid == 32) atomicAdd(&g_sc[1], sred[32]);
}

// ---------------- trace(S^T A S) ----------------
__global__ void trace_kernel(const float* __restrict__ assign, const int* __restrict__ src,
                             const int* __restrict__ dst, int E) {
    int e = blockIdx.x * blockDim.x + threadIdx.x;
    float t = 0.f;
    if (e < E) {
        const float4* a = (const float4*)(assign + (size_t)src[e] * KCL);
        const float4* b = (const float4*)(assign + (size_t)dst[e] * KCL);
        #pragma unroll
        for (int j = 0; j < 4; j++) {
            float4 x = a[j], y = b[j];
            t += x.x * y.x + x.y * y.y + x.z * y.z + x.w * y.w;
        }
    }
    #pragma unroll
    for (int o = 16; o; o >>= 1) t += __shfl_down_sync(0xffffffffu, t, o);
    __shared__ float sw[8];
    if ((threadIdx.x & 31) == 0) sw[threadIdx.x >> 5] = t;
    __syncthreads();
    if (threadIdx.x < 8) {
        float v = sw[threadIdx.x];
        #pragma unroll
        for (int o = 4; o; o >>= 1) v += __shfl_down_sync(0xffu, v, o);
        if (threadIdx.x == 0) atomicAdd(&g_sc[0], v);
    }
}

// ---------------- pooled ----------------
__global__ void pooled_kernel(const float* __restrict__ assign, const float* __restrict__ emb,
                              float* __restrict__ pooled, int N) {
    __shared__ __align__(16) float sA[128 * KCL];
    int tid = threadIdx.x;
    int i0 = blockIdx.x * 128;
    int d = blockIdx.y * 128 + tid;
    for (int idx = tid; idx < 128 * KCL; idx += 128) {
        int gi = i0 + (idx >> 4);
        sA[idx] = (gi < N) ? assign[(size_t)gi * KCL + (idx & 15)] : 0.f;
    }
    __syncthreads();
    float acc[KCL] = {};
    int imax = min(128, N - i0);
    for (int i = 0; i < imax; i++) {
        float ev = emb[(size_t)(i0 + i) * DIM + d];
        const float4* a4 = (const float4*)&sA[i * KCL];
        #pragma unroll
        for (int k4 = 0; k4 < 4; k4++) {
            float4 a = a4[k4];
            acc[k4 * 4 + 0] += a.x * ev;
            acc[k4 * 4 + 1] += a.y * ev;
            acc[k4 * 4 + 2] += a.z * ev;
            acc[k4 * 4 + 3] += a.w * ev;
        }
    }
    #pragma unroll
    for (int k = 0; k < KCL; k++)
        atomicAdd(&pooled[k * DIM + d], acc[k]);
}

// ---------------- final ----------------
__global__ void final_kernel(float* __restrict__ out, int N, float m) {
    float* pooled = out + (size_t)N * KCL;
    int t = threadIdx.x;
    #pragma unroll
    for (int k = 0; k < KCL; k++)
        pooled[k * DIM + t] *= 1.f / (g_cs[k] + 1e-8f);
    if (t == 0) {
        float dd = 0.f, csn = 0.f;
        #pragma unroll
        for (int k = 0; k < KCL; k++) { dd += g_dS[k] * g_dS[k]; csn += g_cs[k] * g_cs[k]; }
        float normalizer = dd / (2.f * m);
        float spectral = -(g_sc[0] - (float)KCL * normalizer) / (2.f * m);
        float collapse = sqrtf(csn) / (float)N * sqrtf((float)KCL) - 1.f;
        float entropy = -g_sc[1] / (float)N;
        float ent_loss = -0.1f * entropy;
        float total = spectral + collapse + ent_loss;
        float* s = pooled + KCL * DIM;
        s[0] = spectral;
        s[1] = collapse;
        s[2] = total;
        s[3] = ent_loss;
    }
}

// ---------------- launch ----------------
extern "C" void kernel_launch(void* const* d_in, const int* in_sizes, int n_in,
                              void* d_out, int out_size) {
    const float* emb  = (const float*)d_in[0];
    const int*   esrc = (const int*)d_in[1];
    const int*   edst = (const int*)d_in[2];
    const float* W1   = (const float*)d_in[3];
    const float* b1   = (const float*)d_in[4];
    const float* W2   = (const float*)d_in[5];
    const float* b2   = (const float*)d_in[6];
    const float* Wa   = (const float*)d_in[7];
    const float* ba   = (const float*)d_in[8];
    float* out = (float*)d_out;

    int E = in_sizes[1];
    int N = in_sizes[0] / DIM;
    float* pooled = out + (size_t)N * KCL;

    float *bufA, *bufB, *bufC;
    __nv_bfloat16 *hi, *lo, *w1thi, *w1tlo, *w2thi, *w2tlo;
    cudaGetSymbolAddress((void**)&bufA, g_bufA);
    cudaGetSymbolAddress((void**)&bufB, g_bufB);
    cudaGetSymbolAddress((void**)&bufC, g_bufC);
    cudaGetSymbolAddress((void**)&hi, g_hi);
    cudaGetSymbolAddress((void**)&lo, g_lo);
    cudaGetSymbolAddress((void**)&w1thi, g_w1t_hi);
    cudaGetSymbolAddress((void**)&w1tlo, g_w1t_lo);
    cudaGetSymbolAddress((void**)&w2thi, g_w2t_hi);
    cudaGetSymbolAddress((void**)&w2tlo, g_w2t_lo);

    int nb256 = (N + 255) / 256;
    int eb256 = (E + 255) / 256;
    int nscan = (N + 255) / 256;
    dim3 g1((N + 127) / 128, HID / 128);
    int gather_blocks = (N * 32 + 255) / 256;
    int zb = nb256 > (KCL * DIM + 255) / 256 ? nb256 : (KCL * DIM + 255) / 256;

    // (1-3) splits (graph-independent)
    split_kernel<<<(N * DIM + 255) / 256, 256>>>(emb, hi, lo, N * DIM);
    splitT_kernel<<<(DIM * HID + 255) / 256, 256>>>(W1, w1thi, w1tlo, DIM, HID);
    splitT_kernel<<<(HID * HID + 255) / 256, 256>>>(W2, w2thi, w2tlo, HID, HID);

    // (4) GEMM1 -> bufA  (launch #4: ncu capture slot)
    mma_gemm_kernel<<<g1, 256>>>(hi, lo, w1thi, w1tlo, bufA, N, DIM, HID);

    // (5-11) zero, degrees, CSR scan/fill, dis
    zero_kernel<<<zb, 256>>>(pooled, N);
    degree_kernel<<<eb256, 256>>>(esrc, edst, E);
    scanA_kernel<<<nscan, 256>>>(N);
    scanB_kernel<<<1, 256>>>(nscan);
    scanC_kernel<<<nscan, 256>>>(N);
    fill_kernel<<<eb256, 256>>>(esrc, edst, E);
    dis_kernel<<<nb256, 256>>>(N);

    // (12) layer-1 aggregation (gather + bias + selu + bf16 split): bufA -> bufB (=x=x_skip), hi/lo
    gather_kernel<<<gather_blocks, 256>>>(bufA, b1, nullptr, bufB, hi, lo, N);

    // (13) GEMM2 on x -> bufA
    mma_gemm_kernel<<<g1, 256>>>(hi, lo, w2thi, w2tlo, bufA, N, HID, HID);

    // (14) layer-2 aggregation (+skip=bufB): bufA -> bufC (=x2)
    gather_kernel<<<gather_blocks, 256>>>(bufA, b2, bufB, bufC, nullptr, nullptr, N);

    // (15) assignments + fused cs/dS/entropy reductions
    assign_kernel<<<(N + 127) / 128, 128>>>(bufC, Wa, ba, out, N);

    // (16) trace over edges
    trace_kernel<<<eb256, 256>>>(out, esrc, edst, E);

    // (17) pooled
    pooled_kernel<<<dim3((N + 127) / 128, DIM / 128), 128>>>(out, emb, pooled, N);

    // (18) scalars
    final_kernel<<<1, DIM>>>(out, N, 0.5f * (float)E);
}

// round 12
// speedup vs baseline: 2.7081x; 1.1662x over previous
#include <cuda_runtime.h>
#include <cuda_bf16.h>
#include <math.h>
#include <stdint.h>

#define DIM 512
#define HID 256
#define KCL 16
#define NMAX 50000
#define EMAX 800000

// ---------------- scratch (device globals: alloc-free rule) ----------------
__device__ float g_bufA[NMAX * HID];   // GEMM outputs
__device__ float g_bufB[NMAX * HID];   // x (= x_skip) after layer-1 gather
__device__ float g_bufC[NMAX * HID];   // x2 after layer-2 gather
__device__ __nv_bfloat16 g_hi[NMAX * HID];   // bf16 split of x (GEMM2 input)
__device__ __nv_bfloat16 g_lo[NMAX * HID];
__device__ __nv_bfloat16 g_w1t_hi[HID * DIM];
__device__ __nv_bfloat16 g_w1t_lo[HID * DIM];
__device__ __nv_bfloat16 g_w2t_hi[HID * HID];
__device__ __nv_bfloat16 g_w2t_lo[HID * HID];
__device__ int   g_degi_src[NMAX];
__device__ int   g_degi_dst[NMAX];
__device__ int   g_rowoff[NMAX];
__device__ int   g_cursor[NMAX];
__device__ int   g_part[256];
__device__ int   g_csr[EMAX];
__device__ float g_deg_src[NMAX];
__device__ float g_dis[NMAX];
__device__ float g_cs[KCL];
__device__ float g_dS[KCL];
__device__ float g_sc[2];              // [0]=trace, [1]=entropy

__device__ __forceinline__ float selu_f(float v) {
    const float alpha = 1.6732632423543772f;
    const float scale = 1.0507009873554805f;
    return (v > 0.f) ? scale * v : scale * alpha * (expf(v) - 1.f);
}

// ---------------- weight split (transposed) ----------------
// W[K][N] -> Wt hi/lo [N][K]
__global__ void splitT_kernel(const float* __restrict__ W, __nv_bfloat16* __restrict__ thi,
                              __nv_bfloat16* __restrict__ tlo, int K, int N) {
    int idx = blockIdx.x * blockDim.x + threadIdx.x;
    if (idx >= K * N) return;
    int k = idx / N, n = idx % N;
    float f = W[idx];
    __nv_bfloat16 h = __float2bfloat16(f);
    thi[n * K + k] = h;
    tlo[n * K + k] = __float2bfloat16(f - __bfloat162float(h));
}

// ---------------- mma helper ----------------
__device__ __forceinline__ void mma16816(float& c0, float& c1, float& c2, float& c3,
                                         uint32_t a0, uint32_t a1, uint32_t a2, uint32_t a3,
                                         uint32_t b0, uint32_t b1) {
    asm volatile("mma.sync.aligned.m16n8k16.row.col.f32.bf16.bf16.f32 "
                 "{%0,%1,%2,%3}, {%4,%5,%6,%7}, {%8,%9}, {%0,%1,%2,%3};"
                 : "+f"(c0), "+f"(c1), "+f"(c2), "+f"(c3)
                 : "r"(a0), "r"(a1), "r"(a2), "r"(a3), "r"(b0), "r"(b1));
}

// ---------------- bf16x3-split tensor-core GEMM, double-buffered ----------------
// A_MODE 0: A is fp32 (split to hi/lo on the fly).  A_MODE 1: A is pre-split bf16 hi/lo.
// C[M,Nd] = A[M,K] @ Bt[Nd,K]^T, fp32 accum, 3-term bf16 split.
// 128x128 tile, 256 threads (2x4 warps of 64x32), BK=32, reg-staged double buffer.
#define SP 40
#define SLAB (128 * SP)
#define GEMM_SMEM (8 * SLAB * 2)   // 8 arrays of 128*SP bf16 = 81920 bytes

template <int A_MODE>
__global__ __launch_bounds__(256, 1)
void mma_gemm_db(const float* __restrict__ Af,
                 const __nv_bfloat16* __restrict__ Ahi, const __nv_bfloat16* __restrict__ Alo,
                 const __nv_bfloat16* __restrict__ Bthi, const __nv_bfloat16* __restrict__ Btlo,
                 float* __restrict__ C, int M, int K, int Nd) {
    extern __shared__ __nv_bfloat16 smem[];
    // layout: [buf][hl] A slabs then B slabs
    __nv_bfloat16* sA = smem;                // (buf*2+hl)*SLAB
    __nv_bfloat16* sB = smem + 4 * SLAB;

    int tid = threadIdx.x;
    int lane = tid & 31, wid = tid >> 5;
    int wm = wid & 1, wn = wid >> 1;
    int row0 = blockIdx.x * 128;
    int col0 = blockIdx.y * 128;
    int qr = lane >> 2, qk = (lane & 3) * 2;

    // load geometry: idx in [0,1024): r = idx>>3 (0..127), seg = idx&7 -> col seg*4
    float4 af_s[4];
    uint2 ah_s[4], al_s[4], bh_s[4], bl_s[4];

    auto load_regs = [&](int k0) {
        #pragma unroll
        for (int it = 0; it < 4; it++) {
            int idx = tid + it * 256;
            int r = idx >> 3, seg = idx & 7;
            int grow = row0 + r;
            if (A_MODE == 0) {
                af_s[it] = (grow < M) ? *(const float4*)(Af + (size_t)grow * K + k0 + seg * 4)
                                      : make_float4(0.f, 0.f, 0.f, 0.f);
            } else {
                if (grow < M) {
                    ah_s[it] = *(const uint2*)(Ahi + (size_t)grow * K + k0 + seg * 4);
                    al_s[it] = *(const uint2*)(Alo + (size_t)grow * K + k0 + seg * 4);
                } else {
                    ah_s[it] = make_uint2(0u, 0u);
                    al_s[it] = make_uint2(0u, 0u);
                }
            }
            int gcol = col0 + r;
            bh_s[it] = *(const uint2*)(Bthi + (size_t)gcol * K + k0 + seg * 4);
            bl_s[it] = *(const uint2*)(Btlo + (size_t)gcol * K + k0 + seg * 4);
        }
    };

    auto store_smem = [&](int buf) {
        __nv_bfloat16* aH = sA + (buf * 2 + 0) * SLAB;
        __nv_bfloat16* aL = sA + (buf * 2 + 1) * SLAB;
        __nv_bfloat16* bH = sB + (buf * 2 + 0) * SLAB;
        __nv_bfloat16* bL = sB + (buf * 2 + 1) * SLAB;
        #pragma unroll
        for (int it = 0; it < 4; it++) {
            int idx = tid + it * 256;
            int r = idx >> 3, seg = idx & 7;
            int off = r * SP + seg * 4;
            if (A_MODE == 0) {
                float f[4] = {af_s[it].x, af_s[it].y, af_s[it].z, af_s[it].w};
                __nv_bfloat16 h[4], l[4];
                #pragma unroll
                for (int j = 0; j < 4; j++) {
                    h[j] = __float2bfloat16(f[j]);
                    l[j] = __float2bfloat16(f[j] - __bfloat162float(h[j]));
                }
                *(uint2*)&aH[off] = *(uint2*)h;
                *(uint2*)&aL[off] = *(uint2*)l;
            } else {
                *(uint2*)&aH[off] = ah_s[it];
                *(uint2*)&aL[off] = al_s[it];
            }
            *(uint2*)&bH[off] = bh_s[it];
            *(uint2*)&bL[off] = bl_s[it];
        }
    };

    float acc[4][4][4] = {};
    const int nk = K >> 5;

    load_regs(0);
    store_smem(0);
    __syncthreads();

    for (int kb = 0; kb < nk; kb++) {
        int buf = kb & 1;
        if (kb + 1 < nk) load_regs((kb + 1) << 5);

        __nv_bfloat16* aH = sA + (buf * 2 + 0) * SLAB;
        __nv_bfloat16* aL = sA + (buf * 2 + 1) * SLAB;
        __nv_bfloat16* bH = sB + (buf * 2 + 0) * SLAB;
        __nv_bfloat16* bL = sB + (buf * 2 + 1) * SLAB;

        #pragma unroll
        for (int kk = 0; kk < 32; kk += 16) {
            uint32_t ah[4][4], al[4][4], bh[4][2], bl[4][2];
            #pragma unroll
            for (int mt = 0; mt < 4; mt++) {
                int m = wm * 64 + mt * 16;
                ah[mt][0] = *(const uint32_t*)&aH[(m + qr) * SP + kk + qk];
                ah[mt][1] = *(const uint32_t*)&aH[(m + qr + 8) * SP + kk + qk];
                ah[mt][2] = *(const uint32_t*)&aH[(m + qr) * SP + kk + qk + 8];
                ah[mt][3] = *(const uint32_t*)&aH[(m + qr + 8) * SP + kk + qk + 8];
                al[mt][0] = *(const uint32_t*)&aL[(m + qr) * SP + kk + qk];
                al[mt][1] = *(const uint32_t*)&aL[(m + qr + 8) * SP + kk + qk];
                al[mt][2] = *(const uint32_t*)&aL[(m + qr) * SP + kk + qk + 8];
                al[mt][3] = *(const uint32_t*)&aL[(m + qr + 8) * SP + kk + qk + 8];
            }
            #pragma unroll
            for (int nt = 0; nt < 4; nt++) {
                int n = wn * 32 + nt * 8;
                bh[nt][0] = *(const uint32_t*)&bH[(n + qr) * SP + kk + qk];
                bh[nt][1] = *(const uint32_t*)&bH[(n + qr) * SP + kk + qk + 8];
                bl[nt][0] = *(const uint32_t*)&bL[(n + qr) * SP + kk + qk];
                bl[nt][1] = *(const uint32_t*)&bL[(n + qr) * SP + kk + qk + 8];
            }
            #pragma unroll
            for (int mt = 0; mt < 4; mt++)
                #pragma unroll
                for (int nt = 0; nt < 4; nt++) {
                    float* c = acc[mt][nt];
                    mma16816(c[0], c[1], c[2], c[3],
                             ah[mt][0], ah[mt][1], ah[mt][2], ah[mt][3], bh[nt][0], bh[nt][1]);
                    mma16816(c[0], c[1], c[2], c[3],
                             ah[mt][0], ah[mt][1], ah[mt][2], ah[mt][3], bl[nt][0], bl[nt][1]);
                    mma16816(c[0], c[1], c[2], c[3],
                             al[mt][0], al[mt][1], al[mt][2], al[mt][3], bh[nt][0], bh[nt][1]);
                }
        }

        if (kb + 1 < nk) store_smem((kb + 1) & 1);
        __syncthreads();
    }

    #pragma unroll
    for (int mt = 0; mt < 4; mt++) {
        #pragma unroll
        for (int half = 0; half < 2; half++) {
            int row = row0 + wm * 64 + mt * 16 + qr + half * 8;
            if (row >= M) continue;
            float* crow = C + (size_t)row * Nd;
            #pragma unroll
            for (int nt = 0; nt < 4; nt++) {
                int col = col0 + wn * 32 + nt * 8 + (lane & 3) * 2;
                crow[col] = acc[mt][nt][half * 2 + 0];
                crow[col + 1] = acc[mt][nt][half * 2 + 1];
            }
        }
    }
}

// ---------------- zero + degrees + CSR build ----------------
__global__ void zero_kernel(float* pooled, int N) {
    int i = blockIdx.x * blockDim.x + threadIdx.x;
    if (i < N) { g_degi_src[i] = 0; g_degi_dst[i] = 0; }
    if (i < KCL * DIM) pooled[i] = 0.f;
    if (i < KCL) { g_cs[i] = 0.f; g_dS[i] = 0.f; }
    if (i < 2) g_sc[i] = 0.f;
}

__global__ void degree_kernel(const int* __restrict__ src, const int* __restrict__ dst, int E) {
    int e = blockIdx.x * blockDim.x + threadIdx.x;
    if (e < E) {
        atomicAdd(&g_degi_src[src[e]], 1);
        atomicAdd(&g_degi_dst[dst[e]], 1);
    }
}

__global__ void scanA_kernel(int N) {
    __shared__ int s[256];
    int i = blockIdx.x * 256 + threadIdx.x;
    int v = (i < N) ? g_degi_dst[i] : 0;
    s[threadIdx.x] = v;
    __syncthreads();
    #pragma unroll
    for (int o = 1; o < 256; o <<= 1) {
        int t = (threadIdx.x >= o) ? s[threadIdx.x - o] : 0;
        __syncthreads();
        s[threadIdx.x] += t;
        __syncthreads();
    }
    if (i < N) g_rowoff[i] = s[threadIdx.x] - v;   // exclusive
    if (threadIdx.x == 255) g_part[blockIdx.x] = s[255];
}

__global__ void scanB_kernel(int nb) {
    __shared__ int s[256];
    int v = (threadIdx.x < nb) ? g_part[threadIdx.x] : 0;
    s[threadIdx.x] = v;
    __syncthreads();
    #pragma unroll
    for (int o = 1; o < 256; o <<= 1) {
        int t = (threadIdx.x >= o) ? s[threadIdx.x - o] : 0;
        __syncthreads();
        s[threadIdx.x] += t;
        __syncthreads();
    }
    if (threadIdx.x < nb) g_part[threadIdx.x] = s[threadIdx.x] - v;  // exclusive
}

__global__ void scanC_kernel(int N) {
    int i = blockIdx.x * 256 + threadIdx.x;
    if (i < N) {
        int r = g_rowoff[i] + g_part[blockIdx.x];
        g_rowoff[i] = r;
        g_cursor[i] = r;
    }
}

__global__ void fill_kernel(const int* __restrict__ src, const int* __restrict__ dst, int E) {
    int e = blockIdx.x * blockDim.x + threadIdx.x;
    if (e >= E) return;
    int pos = atomicAdd(&g_cursor[dst[e]], 1);
    g_csr[pos] = src[e];
}

__global__ void dis_kernel(int N) {
    int i = blockIdx.x * blockDim.x + threadIdx.x;
    if (i < N) {
        g_dis[i] = rsqrtf(1.f + (float)g_degi_dst[i]);
        g_deg_src[i] = (float)g_degi_src[i];
    }
}

// ---------------- CSR gather aggregation + bias + SELU (+skip, +bf16 split) ----------------
__global__ __launch_bounds__(256)
void gather_kernel(const float* __restrict__ X, const float* __restrict__ bias,
                   const float* __restrict__ skip, float* __restrict__ out,
                   __nv_bfloat16* __restrict__ ohi, __nv_bfloat16* __restrict__ olo, int N) {
    int w = (blockIdx.x * blockDim.x + threadIdx.x) >> 5;
    int lane = threadIdx.x & 31;
    if (w >= N) return;
    float dd = g_dis[w];
    float d2 = dd * dd;
    const float4* xs = (const float4*)(X + (size_t)w * HID);
    float4 s0 = xs[lane], s1 = xs[lane + 32];
    float a0x = s0.x * d2, a0y = s0.y * d2, a0z = s0.z * d2, a0w = s0.w * d2;
    float a1x = s1.x * d2, a1y = s1.y * d2, a1z = s1.z * d2, a1w = s1.w * d2;

    int start = g_rowoff[w];
    int cnt = g_degi_dst[w];
    for (int i = 0; i < cnt; i++) {
        int s = __ldg(&g_csr[start + i]);
        float c = g_dis[s] * dd;
        const float4* xr = (const float4*)(X + (size_t)s * HID);
        float4 v0 = xr[lane], v1 = xr[lane + 32];
        a0x += c * v0.x; a0y += c * v0.y; a0z += c * v0.z; a0w += c * v0.w;
        a1x += c * v1.x; a1y += c * v1.y; a1z += c * v1.z; a1w += c * v1.w;
    }

    const float4* b4 = (const float4*)bias;
    float4 b0 = b4[lane], b1 = b4[lane + 32];
    a0x = selu_f(a0x + b0.x); a0y = selu_f(a0y + b0.y);
    a0z = selu_f(a0z + b0.z); a0w = selu_f(a0w + b0.w);
    a1x = selu_f(a1x + b1.x); a1y = selu_f(a1y + b1.y);
    a1z = selu_f(a1z + b1.z); a1w = selu_f(a1w + b1.w);

    if (skip != nullptr) {
        const float4* k4 = (const float4*)(skip + (size_t)w * HID);
        float4 k0 = k4[lane], k1 = k4[lane + 32];
        a0x += k0.x; a0y += k0.y; a0z += k0.z; a0w += k0.w;
        a1x += k1.x; a1y += k1.y; a1z += k1.z; a1w += k1.w;
    }

    float4* o4 = (float4*)(out + (size_t)w * HID);
    o4[lane] = make_float4(a0x, a0y, a0z, a0w);
    o4[lane + 32] = make_float4(a1x, a1y, a1z, a1w);

    if (ohi != nullptr) {
        float f[8] = {a0x, a0y, a0z, a0w, a1x, a1y, a1z, a1w};
        __nv_bfloat16 h[8], l[8];
        #pragma unroll
        for (int j = 0; j < 8; j++) {
            h[j] = __float2bfloat16(f[j]);
            l[j] = __float2bfloat16(f[j] - __bfloat162float(h[j]));
        }
        uint2* hp = (uint2*)(ohi + (size_t)w * HID);
        uint2* lp = (uint2*)(olo + (size_t)w * HID);
        hp[lane] = *(uint2*)&h[0];
        hp[lane + 32] = *(uint2*)&h[4];
        lp[lane] = *(uint2*)&l[0];
        lp[lane + 32] = *(uint2*)&l[4];
    }
}

// ---------------- logits -> softmax -> assignments + fused reductions ----------------
__global__ void assign_kernel(const float* __restrict__ X, const float* __restrict__ Wa,
                              const float* __restrict__ ba, float* __restrict__ out, int N) {
    __shared__ __align__(16) float sWa[HID * KCL];
    __shared__ __align__(16) float sX[128 * 33];
    __shared__ float sred[33];
    int tid = threadIdx.x;
    for (int i = tid; i < HID * KCL; i += 128) sWa[i] = Wa[i];
    if (tid < 33) sred[tid] = 0.f;
    int node = blockIdx.x * 128 + tid;
    float acc[KCL];
    #pragma unroll
    for (int k = 0; k < KCL; k++) acc[k] = ba[k];

    for (int cb = 0; cb < HID; cb += 32) {
        __syncthreads();
        for (int idx = tid; idx < 128 * 32; idx += 128) {
            int ln = idx >> 5, c = idx & 31;
            int gn = blockIdx.x * 128 + ln;
            sX[ln * 33 + c] = (gn < N) ? X[(size_t)gn * HID + cb + c] : 0.f;
        }
        __syncthreads();
        #pragma unroll
        for (int cc = 0; cc < 32; cc++) {
            float xv = sX[tid * 33 + cc];
            const float4* w4 = (const float4*)&sWa[(cb + cc) * KCL];
            #pragma unroll
            for (int k4 = 0; k4 < 4; k4++) {
                float4 w = w4[k4];
                acc[k4 * 4 + 0] += xv * w.x;
                acc[k4 * 4 + 1] += xv * w.y;
                acc[k4 * 4 + 2] += xv * w.z;
                acc[k4 * 4 + 3] += xv * w.w;
            }
        }
    }

    if (node < N) {
        float mx = acc[0];
        #pragma unroll
        for (int k = 1; k < KCL; k++) mx = fmaxf(mx, acc[k]);
        float s = 0.f;
        #pragma unroll
        for (int k = 0; k < KCL; k++) { acc[k] = expf(acc[k] - mx); s += acc[k]; }
        float inv = 1.f / s;
        float ent = 0.f;
        float dgs = g_deg_src[node];
        #pragma unroll
        for (int k = 0; k < KCL; k++) {
            acc[k] *= inv;
            ent += acc[k] * logf(acc[k] + 1e-8f);
        }
        float4* o4 = (float4*)(out + (size_t)node * KCL);
        o4[0] = make_float4(acc[0], acc[1], acc[2], acc[3]);
        o4[1] = make_float4(acc[4], acc[5], acc[6], acc[7]);
        o4[2] = make_float4(acc[8], acc[9], acc[10], acc[11]);
        o4[3] = make_float4(acc[12], acc[13], acc[14], acc[15]);
        #pragma unroll
        for (int k = 0; k < KCL; k++) {
            atomicAdd(&sred[k], acc[k]);
            atomicAdd(&sred[16 + k], dgs * acc[k]);
        }
        atomicAdd(&sred[32], ent);
    }
    __syncthreads();
    if (tid < KCL) {
        atomicAdd(&g_cs[tid], sred[tid]);
        atomicAdd(&g_dS[tid], sred[16 + tid]);
    }
    if (tid == 32) atomicAdd(&g_sc[1], sred[32]);
}

// ---------------- trace(S^T A S) ----------------
__global__ void trace_kernel(const float* __restrict__ assign, const int* __restrict__ src,
                             const int* __restrict__ dst, int E) {
    int e = blockIdx.x * blockDim.x + threadIdx.x;
    float t = 0.f;
    if (e < E) {
        const float4* a = (const float4*)(assign + (size_t)src[e] * KCL);
        const float4* b = (const float4*)(assign + (size_t)dst[e] * KCL);
        #pragma unroll
        for (int j = 0; j < 4; j++) {
            float4 x = a[j], y = b[j];
            t += x.x * y.x + x.y * y.y + x.z * y.z + x.w * y.w;
        }
    }
    #pragma unroll
    for (int o = 16; o; o >>= 1) t += __shfl_down_sync(0xffffffffu, t, o);
    __shared__ float sw[8];
    if ((threadIdx.x & 31) == 0) sw[threadIdx.x >> 5] = t;
    __syncthreads();
    if (threadIdx.x < 8) {
        float v = sw[threadIdx.x];
        #pragma unroll
        for (int o = 4; o; o >>= 1) v += __shfl_down_sync(0xffu, v, o);
        if (threadIdx.x == 0) atomicAdd(&g_sc[0], v);
    }
}

// ---------------- pooled ----------------
__global__ void pooled_kernel(const float* __restrict__ assign, const float* __restrict__ emb,
                              float* __restrict__ pooled, int N) {
    __shared__ __align__(16) float sA[128 * KCL];
    int tid = threadIdx.x;
    int i0 = blockIdx.x * 128;
    int d = blockIdx.y * 128 + tid;
    for (int idx = tid; idx < 128 * KCL; idx += 128) {
        int gi = i0 + (idx >> 4);
        sA[idx] = (gi < N) ? assign[(size_t)gi * KCL + (idx & 15)] : 0.f;
    }
    __syncthreads();
    float acc[KCL] = {};
    int imax = min(128, N - i0);
    for (int i = 0; i < imax; i++) {
        float ev = emb[(size_t)(i0 + i) * DIM + d];
        const float4* a4 = (const float4*)&sA[i * KCL];
        #pragma unroll
        for (int k4 = 0; k4 < 4; k4++) {
            float4 a = a4[k4];
            acc[k4 * 4 + 0] += a.x * ev;
            acc[k4 * 4 + 1] += a.y * ev;
            acc[k4 * 4 + 2] += a.z * ev;
            acc[k4 * 4 + 3] += a.w * ev;
        }
    }
    #pragma unroll
    for (int k = 0; k < KCL; k++)
        atomicAdd(&pooled[k * DIM + d], acc[k]);
}

// ---------------- final ----------------
__global__ void final_kernel(float* __restrict__ out, int N, float m) {
    float* pooled = out + (size_t)N * KCL;
    int t = threadIdx.x;
    #pragma unroll
    for (int k = 0; k < KCL; k++)
        pooled[k * DIM + t] *= 1.f / (g_cs[k] + 1e-8f);
    if (t == 0) {
        float dd = 0.f, csn = 0.f;
        #pragma unroll
        for (int k = 0; k < KCL; k++) { dd += g_dS[k] * g_dS[k]; csn += g_cs[k] * g_cs[k]; }
        float normalizer = dd / (2.f * m);
        float spectral = -(g_sc[0] - (float)KCL * normalizer) / (2.f * m);
        float collapse = sqrtf(csn) / (float)N * sqrtf((float)KCL) - 1.f;
        float entropy = -g_sc[1] / (float)N;
        float ent_loss = -0.1f * entropy;
        float total = spectral + collapse + ent_loss;
        float* s = pooled + KCL * DIM;
        s[0] = spectral;
        s[1] = collapse;
        s[2] = total;
        s[3] = ent_loss;
    }
}

// ---------------- launch ----------------
extern "C" void kernel_launch(void* const* d_in, const int* in_sizes, int n_in,
                              void* d_out, int out_size) {
    const float* emb  = (const float*)d_in[0];
    const int*   esrc = (const int*)d_in[1];
    const int*   edst = (const int*)d_in[2];
    const float* W1   = (const float*)d_in[3];
    const float* b1   = (const float*)d_in[4];
    const float* W2   = (const float*)d_in[5];
    const float* b2   = (const float*)d_in[6];
    const float* Wa   = (const float*)d_in[7];
    const float* ba   = (const float*)d_in[8];
    float* out = (float*)d_out;

    int E = in_sizes[1];
    int N = in_sizes[0] / DIM;
    float* pooled = out + (size_t)N * KCL;

    float *bufA, *bufB, *bufC;
    __nv_bfloat16 *hi, *lo, *w1thi, *w1tlo, *w2thi, *w2tlo;
    cudaGetSymbolAddress((void**)&bufA, g_bufA);
    cudaGetSymbolAddress((void**)&bufB, g_bufB);
    cudaGetSymbolAddress((void**)&bufC, g_bufC);
    cudaGetSymbolAddress((void**)&hi, g_hi);
    cudaGetSymbolAddress((void**)&lo, g_lo);
    cudaGetSymbolAddress((void**)&w1thi, g_w1t_hi);
    cudaGetSymbolAddress((void**)&w1tlo, g_w1t_lo);
    cudaGetSymbolAddress((void**)&w2thi, g_w2t_hi);
    cudaGetSymbolAddress((void**)&w2tlo, g_w2t_lo);

    static int smem_set = 0;
    if (!smem_set) {
        cudaFuncSetAttribute(mma_gemm_db<0>, cudaFuncAttributeMaxDynamicSharedMemorySize, GEMM_SMEM);
        cudaFuncSetAttribute(mma_gemm_db<1>, cudaFuncAttributeMaxDynamicSharedMemorySize, GEMM_SMEM);
        smem_set = 1;
    }

    int nb256 = (N + 255) / 256;
    int eb256 = (E + 255) / 256;
    int nscan = (N + 255) / 256;
    dim3 g1((N + 127) / 128, HID / 128);
    int gather_blocks = (N * 32 + 255) / 256;
    int zb = nb256 > (KCL * DIM + 255) / 256 ? nb256 : (KCL * DIM + 255) / 256;

    // (1-3) weight splits + zero (graph-independent)
    splitT_kernel<<<(DIM * HID + 255) / 256, 256>>>(W1, w1thi, w1tlo, DIM, HID);
    splitT_kernel<<<(HID * HID + 255) / 256, 256>>>(W2, w2thi, w2tlo, HID, HID);
    zero_kernel<<<zb, 256>>>(pooled, N);

    // (4) GEMM1: fp32 emb -> on-the-fly split -> bufA   (ncu capture slot)
    mma_gemm_db<0><<<g1, 256, GEMM_SMEM>>>(emb, nullptr, nullptr, w1thi, w1tlo, bufA, N, DIM, HID);

    // (5-10) degrees, CSR scan/fill, dis
    degree_kernel<<<eb256, 256>>>(esrc, edst, E);
    scanA_kernel<<<nscan, 256>>>(N);
    scanB_kernel<<<1, 256>>>(nscan);
    scanC_kernel<<<nscan, 256>>>(N);
    fill_kernel<<<eb256, 256>>>(esrc, edst, E);
    dis_kernel<<<nb256, 256>>>(N);

    // (11) layer-1 aggregation (gather + bias + selu + bf16 split): bufA -> bufB (=x=x_skip), hi/lo
    gather_kernel<<<gather_blocks, 256>>>(bufA, b1, nullptr, bufB, hi, lo, N);

    // (12) GEMM2 on pre-split x -> bufA
    mma_gemm_db<1><<<g1, 256, GEMM_SMEM>>>(nullptr, hi, lo, w2thi, w2tlo, bufA, N, HID, HID);

    // (13) layer-2 aggregation (+skip=bufB): bufA -> bufC (=x2)
    gather_kernel<<<gather_blocks, 256>>>(bufA, b2, bufB, bufC, nullptr, nullptr, N);

    // (14) assignments + fused cs/dS/entropy reductions
    assign_kernel<<<(N + 127) / 128, 128>>>(bufC, Wa, ba, out, N);

    // (15) trace over edges
    trace_kernel<<<eb256, 256>>>(out, esrc, edst, E);

    // (16) pooled
    pooled_kernel<<<dim3((N + 127) / 128, DIM / 128), 128>>>(out, emb, pooled, N);

    // (17) scalars
    final_kernel<<<1, DIM>>>(out, N, 0.5f * (float)E);
}